// round 12
// baseline (speedup 1.0000x reference)
#include <cuda_runtime.h>
#include <cuda_fp16.h>
#include <cstdint>

// ---------------- problem constants ----------------
#define N_TOTAL   4096
#define N_IN      1024
#define N_HID     2944
#define N_OUT     128
#define N_MROWS   3072          // matrix rows: nodes 1024..4095
#define BATCH     32
#define T_ITERS   100
#define DT_C      0.05f

// ---------------- kernel config --------------------
#define MAIN_BLOCKS   148
#define MAIN_THREADS  1024
#define MAIN_WARPS    (MAIN_THREADS / 32)              // 32
#define TOTAL_WARPS   (MAIN_BLOCKS * MAIN_WARPS)       // 4736

#define MAX_NNZ   (2 * 1024 * 1024)                    // expected ~815k padded
#define SMEM_CAP  256                                  // pairs per warp in smem
#define SMEM_BYTES (MAIN_WARPS * SMEM_CAP * 8)         // 64 KB dynamic smem
#define NSLOTS    8                                    // max chunks spanning a row

// pair word0 layout: [30:19]=row (12b), [18:7]=col*128 byte offset (col<<7)
// fp16 mirror row stride is 64 B -> mirror offset = (packed & OFF_MASK) >> 1
#define OFF_MASK  0x0007FF80u

// prep mega-kernel block ranges (blockDim = 32x8 = 256)
#define PREP_NOISE_BLKS  ((N_TOTAL / 32) * T_ITERS)    // 12800
#define PREP_X_BLKS      (N_IN / 32)                   // 32
#define PREP_CNT_BLKS    (N_MROWS / 8)                 // 384
#define PREP_BLKS        (PREP_NOISE_BLKS + PREP_X_BLKS + PREP_CNT_BLKS)

// ---------------- device scratch (no allocs allowed) ----------------
__device__ __align__(16) uint2 g_pairs[MAX_NNZ];   // {row<<19|col<<7, f32 bits}
__device__ int  g_row_start[N_MROWS + 1];          // padded-even prefix
__device__ int  g_row_cnt[N_MROWS];                // padded (even) counts
__device__ int  g_row_w0[N_MROWS];                 // first warp covering row
__device__ int  g_row_nslots[N_MROWS];             // #chunks spanning row (0..8)
__device__ int  g_W;                               // pairs per warp chunk (even)

__device__ float g_part[N_MROWS * NSLOTS * BATCH]; // [row][slot][b] partial phis
__device__ float g_s0[N_TOTAL * BATCH];            // fp32 state ping [node][batch]
__device__ float g_s1[N_TOTAL * BATCH];            // fp32 state pong
__device__ __align__(16) __half g_sm0[N_TOTAL * BATCH];  // fp16 mirror ping
__device__ __align__(16) __half g_sm1[N_TOTAL * BATCH];  // fp16 mirror pong
__device__ float g_noiseT[(size_t)T_ITERS * N_TOTAL * BATCH]; // [t][node][b]
__device__ float g_xT[N_IN * BATCH];               // [node][b]
__device__ float g_inv_tau[N_TOTAL];

// flag barrier state (no same-address atomics -> no L2-atom serialization)
__device__ volatile unsigned g_flags[MAIN_BLOCKS]; // per-CTA arrival flag (gen+1)
__device__ volatile unsigned g_bar_gen;            // released generation

// ---------------- software grid barrier (flag-based) ----------------
// Arrival: thread0 __threadfence (emits CCTL.IVALL -> whole-SM L1D invalidate
// + publishes this CTA's writes), then STG its flag = gen+1. CTA0's warp0
// polls all flags (volatile, L1-bypassing) and releases g_bar_gen = gen+1.
// No loads fill L1 between the IVALL and the release, so post-barrier plain
// L1-cached loads of cross-SM data are safe (validated rounds 6-11).
__device__ __forceinline__ void grid_barrier() {
    __syncthreads();
    if (blockIdx.x == 0) {
        if (threadIdx.x < 32) {
            if (threadIdx.x == 0) __threadfence();
            const unsigned gen = g_bar_gen;
            bool done = false;
            while (!done) {
                bool ok = true;
                for (int i = threadIdx.x; i < MAIN_BLOCKS; i += 32)
                    ok &= (i == 0) || (g_flags[i] == gen + 1u);
                done = __all_sync(0xffffffffu, ok);
            }
            if (threadIdx.x == 0) g_bar_gen = gen + 1u;
        }
        __syncthreads();
    } else {
        if (threadIdx.x == 0) {
            __threadfence();
            const unsigned gen = g_bar_gen;
            g_flags[blockIdx.x] = gen + 1u;
            while (g_bar_gen == gen) { }
        }
        __syncthreads();
    }
}

// ---------------- L0: mega-prep (transposes + counts + inv_tau) ----------------
__global__ void prep_kernel(const float* __restrict__ mask,
                            const float* __restrict__ tau,
                            const float* __restrict__ noise,
                            const float* __restrict__ x) {
    __shared__ float tile[32][33];
    const unsigned blk = blockIdx.x;

    if (blk < PREP_NOISE_BLKS) {
        const int t  = blk >> 7;               // /128
        const int i0 = (blk & 127) * 32;
        for (int bb = threadIdx.y; bb < 32; bb += 8)
            tile[bb][threadIdx.x] =
                noise[((size_t)t * BATCH + bb) * N_TOTAL + i0 + threadIdx.x];
        __syncthreads();
        for (int ii = threadIdx.y; ii < 32; ii += 8)
            g_noiseT[((size_t)t * N_TOTAL + i0 + ii) * BATCH + threadIdx.x] =
                tile[threadIdx.x][ii];
        return;
    }
    if (blk < PREP_NOISE_BLKS + PREP_X_BLKS) {
        const int xb = blk - PREP_NOISE_BLKS;
        const int i0 = xb * 32;
        for (int bb = threadIdx.y; bb < 32; bb += 8)
            tile[bb][threadIdx.x] = x[(size_t)bb * N_IN + i0 + threadIdx.x];
        __syncthreads();
        for (int ii = threadIdx.y; ii < 32; ii += 8)
            g_xT[(i0 + ii) * BATCH + threadIdx.x] = tile[threadIdx.x][ii];
        const int gt = xb * 256 + threadIdx.y * 32 + threadIdx.x;
        if (gt < N_TOTAL) g_inv_tau[gt] = 1.0f / tau[gt];
        return;
    }
    // row counts: warp per matrix row
    const int warp = (blk - PREP_NOISE_BLKS - PREP_X_BLKS) * 8 + threadIdx.y;
    const int lane = threadIdx.x;
    if (warp >= N_MROWS) return;
    const float* __restrict__ mrow = mask + (size_t)(N_IN + warp) * N_TOTAL;
    int cnt = 0;
    for (int j = lane; j < N_TOTAL; j += 32) {
        unsigned b = __ballot_sync(0xffffffffu, mrow[j] != 0.0f);
        cnt += __popc(b);
    }
    if (lane == 0) g_row_cnt[warp] = (cnt + 1) & ~1;   // pad to even
}

// ---------------- L1: exclusive prefix over 3072 padded counts ----------------
__global__ void scan_kernel() {
    __shared__ int sh[32];
    const int t = threadIdx.x;      // 1024 threads
    int off = 0;
    for (int seg = 0; seg < 3; ++seg) {
        int v = g_row_cnt[seg * 1024 + t];
        int xv = v;
        #pragma unroll
        for (int d = 1; d < 32; d <<= 1) {
            int y = __shfl_up_sync(0xffffffffu, xv, d);
            if ((t & 31) >= d) xv += y;
        }
        if ((t & 31) == 31) sh[t >> 5] = xv;
        __syncthreads();
        if (t < 32) {
            int x2 = sh[t];
            #pragma unroll
            for (int d = 1; d < 32; d <<= 1) {
                int y = __shfl_up_sync(0xffffffffu, x2, d);
                if (t >= d) x2 += y;
            }
            sh[t] = x2;
        }
        __syncthreads();
        const int incl = xv + ((t >= 32) ? sh[(t >> 5) - 1] : 0);
        g_row_start[seg * 1024 + t] = off + incl - v;
        const int segtotal = sh[31];
        __syncthreads();
        off += segtotal;
    }
    if (t == 0) {
        g_row_start[N_MROWS] = off;
        int w = (off + TOTAL_WARPS - 1) / TOTAL_WARPS;
        w = (w + 1) & ~1;
        if (w < 2) w = 2;
        g_W = w;
    }
}

// ---------------- L2: fill flat pair array + per-row chunk metadata ----------------
__global__ void fill_kernel(const float* __restrict__ J,
                            const float* __restrict__ mask) {
    const int warp = (blockIdx.x * blockDim.x + threadIdx.x) >> 5;
    const int lane = threadIdx.x & 31;
    if (warp >= N_MROWS) return;
    const int row = N_IN + warp;
    const float* __restrict__ mrow = mask + (size_t)row * N_TOTAL;
    const float* __restrict__ jrow = J    + (size_t)row * N_TOTAL;
    const int base = g_row_start[warp];
    const unsigned rtag = (unsigned)warp << 19;

    int pos = base;
    for (int j = lane; j < N_TOTAL; j += 32) {
        const float mv = mrow[j];
        const bool  nz = (mv != 0.0f);
        unsigned b = __ballot_sync(0xffffffffu, nz);
        if (nz) {
            int idx = pos + __popc(b & ((1u << lane) - 1u));
            g_pairs[idx] = make_uint2(rtag | ((unsigned)j << 7),
                                      __float_as_uint(jrow[j] * mv));
        }
        pos += __popc(b);
    }
    const int cnt = pos - base;
    if (lane == 0) {
        if (cnt & 1) g_pairs[base + cnt] = make_uint2(rtag, 0u);  // pad, val=0
        const int cnt_pad = (cnt + 1) & ~1;
        const int W = g_W;
        int w0 = 0, nsl = 0;
        if (cnt_pad > 0) {
            w0  = base / W;
            nsl = (base + cnt_pad - 1) / W - w0 + 1;
            if (nsl > NSLOTS) nsl = NSLOTS;
        }
        g_row_w0[warp]     = w0;
        g_row_nslots[warp] = nsl;
    }
}

// ---------------- L3: main persistent recurrence kernel ----------------
// Phase1: warp w owns flat pairs [w*W,(w+1)*W) (smem-staged once).
//   Paired-lane mapping: lanes 0-15 handle even pairs, 16-31 odd pairs; each
//   lane gathers half2 (2 batches) from the fp16 state mirror -> one LDG.32
//   covers 2 nnz, 64 B line per nnz (half the fp32 traffic). All accumulation
//   stays fp32; J values stay fp32.
// Phase2: warp=node, lane=batch; combine <=8 partials in fixed order, update
//   fp32 state, and write the fp16 mirror for the next iteration's gathers.
__global__ void __launch_bounds__(MAIN_THREADS, 1)
soen_main_kernel(const float* __restrict__ gamma,
                 const float* __restrict__ flux,
                 float* __restrict__ out) {
    extern __shared__ uint2 sh_pairs[];
    const int lane    = threadIdx.x & 31;
    const int wcta    = threadIdx.x >> 5;
    const int gwarp   = blockIdx.x * MAIN_WARPS + wcta;
    const unsigned hs = lane & 16;                 // half select
    const int bpair   = lane & 15;                 // batch pair index

    const int W     = g_W;
    const int total = g_row_start[N_MROWS];
    const int cbase = gwarp * W;
    int n = total - cbase;
    if (n > W) n = W;
    if (n < 0) n = 0;

    // stage this warp's chunk into smem (once; static schedule)
    const uint2* __restrict__ pbase;
    {
        uint2* mych = sh_pairs + wcta * SMEM_CAP;
        for (int j = lane; j < n; j += 32) mych[j] = g_pairs[cbase + j];
        __syncwarp();
        pbase = mych;
    }

    // zero-init fp32 s(t=0) (mirror(t=0) is never read: phase1 skipped at t=0)
    for (int idx = blockIdx.x * MAIN_THREADS + threadIdx.x;
         idx < N_TOTAL * BATCH; idx += MAIN_BLOCKS * MAIN_THREADS)
        g_s0[idx] = 0.0f;
    grid_barrier();

    for (int t = 0; t < T_ITERS; ++t) {
        const float*  src  = (t & 1) ? g_s1  : g_s0;
        float*        dst  = (t & 1) ? g_s0  : g_s1;
        const __half* srcm = (t & 1) ? g_sm1 : g_sm0;
        __half*       dstm = (t & 1) ? g_sm0 : g_sm1;
        const char* srcb2 = (const char*)srcm + bpair * 4;  // half2 per lane

        // ---------- phase 1: balanced gather of partial phis ----------
        if (t > 0) {                                // s(0)=0 -> partials all zero
            int pos = 0;
            while (pos < n) {
                const unsigned h0 = pbase[pos].x;
                const int row = (int)(h0 >> 19);
                int run_end = g_row_start[row + 1] - cbase;
                if (run_end > n) run_end = n;
                const int slot = gwarp - g_row_w0[row];

                float ax0 = 0.0f, ay0 = 0.0f, ax1 = 0.0f, ay1 = 0.0f;
                int k = pos;
                for (; k + 8 <= run_end; k += 8) {
                    const uint4 qa = *reinterpret_cast<const uint4*>(pbase + k);
                    const uint4 qb = *reinterpret_cast<const uint4*>(pbase + k + 2);
                    const uint4 qc = *reinterpret_cast<const uint4*>(pbase + k + 4);
                    const uint4 qd = *reinterpret_cast<const uint4*>(pbase + k + 6);
                    const unsigned oa = ((hs ? qa.z : qa.x) & OFF_MASK) >> 1;
                    const unsigned ob = ((hs ? qb.z : qb.x) & OFF_MASK) >> 1;
                    const unsigned oc = ((hs ? qc.z : qc.x) & OFF_MASK) >> 1;
                    const unsigned od = ((hs ? qd.z : qd.x) & OFF_MASK) >> 1;
                    const float va = __uint_as_float(hs ? qa.w : qa.y);
                    const float vb = __uint_as_float(hs ? qb.w : qb.y);
                    const float vc = __uint_as_float(hs ? qc.w : qc.y);
                    const float vd = __uint_as_float(hs ? qd.w : qd.y);
                    const __half2 ha = *reinterpret_cast<const __half2*>(srcb2 + oa);
                    const __half2 hb = *reinterpret_cast<const __half2*>(srcb2 + ob);
                    const __half2 hc = *reinterpret_cast<const __half2*>(srcb2 + oc);
                    const __half2 hd = *reinterpret_cast<const __half2*>(srcb2 + od);
                    const float2 sa = __half22float2(ha);
                    const float2 sb = __half22float2(hb);
                    const float2 sc = __half22float2(hc);
                    const float2 sd = __half22float2(hd);
                    ax0 = fmaf(va, sa.x, ax0);  ay0 = fmaf(va, sa.y, ay0);
                    ax1 = fmaf(vb, sb.x, ax1);  ay1 = fmaf(vb, sb.y, ay1);
                    ax0 = fmaf(vc, sc.x, ax0);  ay0 = fmaf(vc, sc.y, ay0);
                    ax1 = fmaf(vd, sd.x, ax1);  ay1 = fmaf(vd, sd.y, ay1);
                }
                for (; k < run_end; k += 2) {        // runs are even-length
                    const uint4 q = *reinterpret_cast<const uint4*>(pbase + k);
                    const unsigned o = ((hs ? q.z : q.x) & OFF_MASK) >> 1;
                    const float    v = __uint_as_float(hs ? q.w : q.y);
                    const float2  sv = __half22float2(
                        *reinterpret_cast<const __half2*>(srcb2 + o));
                    ax0 = fmaf(v, sv.x, ax0);
                    ay0 = fmaf(v, sv.y, ay0);
                }
                ax0 += ax1;  ay0 += ay1;
                ax0 += __shfl_xor_sync(0xffffffffu, ax0, 16);
                ay0 += __shfl_xor_sync(0xffffffffu, ay0, 16);
                if (hs == 0 && slot >= 0 && slot < NSLOTS)
                    *reinterpret_cast<float2*>(
                        g_part + ((row * NSLOTS) + slot) * BATCH + bpair * 2) =
                        make_float2(ax0, ay0);
                pos = run_end;
            }
            grid_barrier();
        }

        // ---------- phase 2: combine + activation + state update ----------
        const float* __restrict__ nzT = g_noiseT + (size_t)t * (N_TOTAL * BATCH);
        const int node = gwarp;                       // 4736 warps >= 4096 nodes
        if (node < N_TOTAL) {
            const int nb = node * BATCH + lane;
            float phi = 0.0f;
            if (node >= N_IN && t > 0) {
                const int r   = node - N_IN;
                const int nsl = g_row_nslots[r];
                const float* pp = g_part + (r * NSLOTS) * BATCH + lane;
                #pragma unroll
                for (int sl = 0; sl < NSLOTS; ++sl)
                    if (sl < nsl) phi += pp[sl * BATCH];
            }
            phi += flux[node];
            if (node < N_IN) phi += g_xT[nb];
            phi += nzT[nb];
            phi = fminf(fmaxf(phi, -0.5f), 0.5f);
            const float phip = (phi >= 0.5f) ? -0.5f : phi;  // periodic wrap

            const float sold = src[nb];
            const float gact = tanhf(phip) * (1.0f - sold);
            float snew = sold + DT_C * (gamma[node] * gact - sold * g_inv_tau[node]);
            snew = fminf(fmaxf(snew, -1.0f), 1.0f);
            dst[nb]  = snew;
            dstm[nb] = __float2half_rn(snew);         // fp16 mirror for gathers

            if (t == T_ITERS - 1 && node >= N_IN + N_HID)
                out[(size_t)lane * N_OUT + (node - (N_IN + N_HID))] = snew;
        }
        if (t != T_ITERS - 1) grid_barrier();
    }
}

// ---------------- launch: 4 launches, main at index 3 (ncu capture slot) ----
extern "C" void kernel_launch(void* const* d_in, const int* in_sizes, int n_in,
                              void* d_out, int out_size) {
    const float* x     = (const float*)d_in[0];   // [32, 1024]
    const float* J     = (const float*)d_in[1];   // [4096, 4096]
    const float* gamma = (const float*)d_in[2];   // [4096]
    const float* tau   = (const float*)d_in[3];   // [4096]
    const float* flux  = (const float*)d_in[4];   // [4096]
    const float* mask  = (const float*)d_in[5];   // [4096, 4096]
    const float* noise = (const float*)d_in[6];   // [100, 32, 4096]
    float* out = (float*)d_out;                   // [32, 128]
    (void)in_sizes; (void)n_in; (void)out_size;

    cudaFuncSetAttribute(soen_main_kernel,
                         cudaFuncAttributeMaxDynamicSharedMemorySize, SMEM_BYTES);

    prep_kernel<<<PREP_BLKS, dim3(32, 8)>>>(mask, tau, noise, x);      // idx 0
    scan_kernel<<<1, 1024>>>();                                        // idx 1
    fill_kernel<<<(N_MROWS * 32 + 255) / 256, 256>>>(J, mask);         // idx 2
    soen_main_kernel<<<MAIN_BLOCKS, MAIN_THREADS, SMEM_BYTES>>>(       // idx 3
        gamma, flux, out);
}

// round 13
// speedup vs baseline: 1.3610x; 1.3610x over previous
#include <cuda_runtime.h>
#include <cuda_fp16.h>
#include <cstdint>

// ---------------- problem constants ----------------
#define N_TOTAL   4096
#define N_IN      1024
#define N_HID     2944
#define N_OUT     128
#define N_MROWS   3072          // matrix rows: nodes 1024..4095
#define BATCH     32
#define T_ITERS   100
#define DT_C      0.05f

// ---------------- kernel config --------------------
#define MAIN_BLOCKS   148
#define MAIN_THREADS  1024
#define MAIN_WARPS    (MAIN_THREADS / 32)              // 32
#define TOTAL_WARPS   (MAIN_BLOCKS * MAIN_WARPS)       // 4736

#define NGROUPS        2                               // batch groups of 16
#define GB             16                              // batches per group
#define CTAS_PER_GRP   (MAIN_BLOCKS / NGROUPS)         // 74
#define WARPS_PER_GRP  (CTAS_PER_GRP * MAIN_WARPS)     // 2368

#define MAX_NNZ   (2 * 1024 * 1024)                    // expected ~811k padded
#define SMEM_CAP  368                                  // pairs per warp in smem
#define SLAB_BYTES (N_TOTAL * GB * 2)                  // 128 KB fp16 state slab
#define PAIR_BYTES (MAIN_WARPS * SMEM_CAP * 8)         // 94.2 KB
#define SMEM_BYTES (SLAB_BYTES + PAIR_BYTES)           // 222.2 KB < 227 KB cap
#define NSLOTS    4                                    // max chunks spanning a row

// pair word0 layout: [31:20]=row (12b), [16:5]=col*32 byte offset (col<<5)
#define OFF_MASK  0x0001FFE0u

// prep mega-kernel block ranges (blockDim = 32x8 = 256)
#define PREP_NOISE_BLKS  ((N_TOTAL / 32) * T_ITERS)    // 12800
#define PREP_X_BLKS      (N_IN / 32)                   // 32
#define PREP_CNT_BLKS    (N_MROWS / 8)                 // 384
#define PREP_BLKS        (PREP_NOISE_BLKS + PREP_X_BLKS + PREP_CNT_BLKS)

// ---------------- device scratch (no allocs allowed) ----------------
__device__ __align__(16) uint2 g_pairs[MAX_NNZ];   // {row<<20|col<<5, f32 bits}
__device__ int  g_row_start[N_MROWS + 1];          // padded-even prefix
__device__ int  g_row_cnt[N_MROWS];                // padded (even) counts
__device__ int  g_row_w0[N_MROWS];                 // first group-warp covering row
__device__ int  g_row_nslots[N_MROWS];             // #chunks spanning row (0..4)
__device__ int  g_W;                               // pairs per warp chunk (even)

__device__ float g_part[NGROUPS * N_MROWS * NSLOTS * GB]; // [g][row][slot][16]
__device__ float g_s0[N_TOTAL * BATCH];            // fp32 state ping [node][batch]
__device__ float g_s1[N_TOTAL * BATCH];            // fp32 state pong
// fp16 mirrors, layout [g][node][16] so each group's slab is one contiguous 128KB
__device__ __align__(16) __half g_sm0[NGROUPS * N_TOTAL * GB];
__device__ __align__(16) __half g_sm1[NGROUPS * N_TOTAL * GB];
__device__ float g_noiseT[(size_t)T_ITERS * N_TOTAL * BATCH]; // [t][node][b]
__device__ float g_xT[N_IN * BATCH];               // [node][b]
__device__ float g_inv_tau[N_TOTAL];

// flag barrier state (no same-address atomics -> no L2-atom serialization)
__device__ volatile unsigned g_flags[MAIN_BLOCKS];
__device__ volatile unsigned g_bar_gen;

// ---------------- software grid barrier (flag-based) ----------------
// Arrival: thread0 __threadfence (emits CCTL.IVALL -> whole-SM L1D invalidate
// + publishes this CTA's writes), then STG its flag. CTA0's warp0 polls all
// flags (volatile, L1-bypassing) and releases g_bar_gen. No loads fill L1
// between the IVALL and the release, so post-barrier plain L1-cached loads of
// cross-SM data are safe (validated rounds 6-12).
__device__ __forceinline__ void grid_barrier() {
    __syncthreads();
    if (blockIdx.x == 0) {
        if (threadIdx.x < 32) {
            if (threadIdx.x == 0) __threadfence();
            const unsigned gen = g_bar_gen;
            bool done = false;
            while (!done) {
                bool ok = true;
                for (int i = threadIdx.x; i < MAIN_BLOCKS; i += 32)
                    ok &= (i == 0) || (g_flags[i] == gen + 1u);
                done = __all_sync(0xffffffffu, ok);
            }
            if (threadIdx.x == 0) g_bar_gen = gen + 1u;
        }
        __syncthreads();
    } else {
        if (threadIdx.x == 0) {
            __threadfence();
            const unsigned gen = g_bar_gen;
            g_flags[blockIdx.x] = gen + 1u;
            while (g_bar_gen == gen) { }
        }
        __syncthreads();
    }
}

// ---------------- L0: mega-prep (transposes + counts + inv_tau) ----------------
__global__ void prep_kernel(const float* __restrict__ mask,
                            const float* __restrict__ tau,
                            const float* __restrict__ noise,
                            const float* __restrict__ x) {
    __shared__ float tile[32][33];
    const unsigned blk = blockIdx.x;

    if (blk < PREP_NOISE_BLKS) {
        const int t  = blk >> 7;               // /128
        const int i0 = (blk & 127) * 32;
        for (int bb = threadIdx.y; bb < 32; bb += 8)
            tile[bb][threadIdx.x] =
                noise[((size_t)t * BATCH + bb) * N_TOTAL + i0 + threadIdx.x];
        __syncthreads();
        for (int ii = threadIdx.y; ii < 32; ii += 8)
            g_noiseT[((size_t)t * N_TOTAL + i0 + ii) * BATCH + threadIdx.x] =
                tile[threadIdx.x][ii];
        return;
    }
    if (blk < PREP_NOISE_BLKS + PREP_X_BLKS) {
        const int xb = blk - PREP_NOISE_BLKS;
        const int i0 = xb * 32;
        for (int bb = threadIdx.y; bb < 32; bb += 8)
            tile[bb][threadIdx.x] = x[(size_t)bb * N_IN + i0 + threadIdx.x];
        __syncthreads();
        for (int ii = threadIdx.y; ii < 32; ii += 8)
            g_xT[(i0 + ii) * BATCH + threadIdx.x] = tile[threadIdx.x][ii];
        const int gt = xb * 256 + threadIdx.y * 32 + threadIdx.x;
        if (gt < N_TOTAL) g_inv_tau[gt] = 1.0f / tau[gt];
        return;
    }
    // row counts: warp per matrix row
    const int warp = (blk - PREP_NOISE_BLKS - PREP_X_BLKS) * 8 + threadIdx.y;
    const int lane = threadIdx.x;
    if (warp >= N_MROWS) return;
    const float* __restrict__ mrow = mask + (size_t)(N_IN + warp) * N_TOTAL;
    int cnt = 0;
    for (int j = lane; j < N_TOTAL; j += 32) {
        unsigned b = __ballot_sync(0xffffffffu, mrow[j] != 0.0f);
        cnt += __popc(b);
    }
    if (lane == 0) g_row_cnt[warp] = (cnt + 1) & ~1;   // pad to even
}

// ---------------- L1: exclusive prefix over 3072 padded counts ----------------
__global__ void scan_kernel() {
    __shared__ int sh[32];
    const int t = threadIdx.x;      // 1024 threads
    int off = 0;
    for (int seg = 0; seg < 3; ++seg) {
        int v = g_row_cnt[seg * 1024 + t];
        int xv = v;
        #pragma unroll
        for (int d = 1; d < 32; d <<= 1) {
            int y = __shfl_up_sync(0xffffffffu, xv, d);
            if ((t & 31) >= d) xv += y;
        }
        if ((t & 31) == 31) sh[t >> 5] = xv;
        __syncthreads();
        if (t < 32) {
            int x2 = sh[t];
            #pragma unroll
            for (int d = 1; d < 32; d <<= 1) {
                int y = __shfl_up_sync(0xffffffffu, x2, d);
                if (t >= d) x2 += y;
            }
            sh[t] = x2;
        }
        __syncthreads();
        const int incl = xv + ((t >= 32) ? sh[(t >> 5) - 1] : 0);
        g_row_start[seg * 1024 + t] = off + incl - v;
        const int segtotal = sh[31];
        __syncthreads();
        off += segtotal;
    }
    if (t == 0) {
        g_row_start[N_MROWS] = off;
        int w = (off + WARPS_PER_GRP - 1) / WARPS_PER_GRP;
        w = (w + 1) & ~1;
        if (w < 2) w = 2;
        g_W = w;
    }
}

// ---------------- L2: fill flat pair array + per-row chunk metadata ----------------
__global__ void fill_kernel(const float* __restrict__ J,
                            const float* __restrict__ mask) {
    const int warp = (blockIdx.x * blockDim.x + threadIdx.x) >> 5;
    const int lane = threadIdx.x & 31;
    if (warp >= N_MROWS) return;
    const int row = N_IN + warp;
    const float* __restrict__ mrow = mask + (size_t)row * N_TOTAL;
    const float* __restrict__ jrow = J    + (size_t)row * N_TOTAL;
    const int base = g_row_start[warp];
    const unsigned rtag = (unsigned)warp << 20;

    int pos = base;
    for (int j = lane; j < N_TOTAL; j += 32) {
        const float mv = mrow[j];
        const bool  nz = (mv != 0.0f);
        unsigned b = __ballot_sync(0xffffffffu, nz);
        if (nz) {
            int idx = pos + __popc(b & ((1u << lane) - 1u));
            g_pairs[idx] = make_uint2(rtag | ((unsigned)j << 5),
                                      __float_as_uint(jrow[j] * mv));
        }
        pos += __popc(b);
    }
    const int cnt = pos - base;
    if (lane == 0) {
        if (cnt & 1) g_pairs[base + cnt] = make_uint2(rtag, 0u);  // pad, val=0
        const int cnt_pad = (cnt + 1) & ~1;
        const int W = g_W;
        int w0 = 0, nsl = 0;
        if (cnt_pad > 0) {
            w0  = base / W;
            nsl = (base + cnt_pad - 1) / W - w0 + 1;
            if (nsl > NSLOTS) nsl = NSLOTS;
        }
        g_row_w0[warp]     = w0;
        g_row_nslots[warp] = nsl;
    }
}

// ---------------- L3: main persistent recurrence kernel ----------------
// Group g = blockIdx&1 owns batches [16g,16g+16). Each CTA keeps its group's
// FULL fp16 state slab [4096 cols][16 b] (128 KB smem), refilled per iter by a
// straight 128 KB sequential copy of the fp16 mirror (same linear layout).
// Phase1: group-warp wg owns flat pairs [wg*W,(wg+1)*W) (smem). Lane map
//   (p = lane>>2 nnz-octet, q = lane&3 batch-quad): one LDS.64 per lane serves
//   8 nnz per warp instruction; pairs broadcast across 4-lane quads. fp32
//   accumulate; 3x shfl_xor reduce over p; lanes p==0 store float4 partials.
// Phase2: warp=node, lane=batch32; combine <=4 partials per group in fixed
//   order, update fp32 state, write fp16 mirror [g][node][16].
__global__ void __launch_bounds__(MAIN_THREADS, 1)
soen_main_kernel(const float* __restrict__ gamma,
                 const float* __restrict__ flux,
                 float* __restrict__ out) {
    extern __shared__ char smem_raw[];
    char*  slab     = smem_raw;                        // 128 KB fp16 state
    uint2* sh_pairs = (uint2*)(smem_raw + SLAB_BYTES); // pair chunks

    const int lane  = threadIdx.x & 31;
    const int wcta  = threadIdx.x >> 5;
    const int gwarp = blockIdx.x * MAIN_WARPS + wcta;  // phase2 id
    const int grp   = blockIdx.x & 1;                  // batch group
    const int wg    = (blockIdx.x >> 1) * MAIN_WARPS + wcta; // group-warp id
    const int p     = lane >> 2;                       // nnz octet position 0..7
    const int q     = lane & 3;                        // batch quad 0..3

    const int W     = g_W;
    const int total = g_row_start[N_MROWS];
    const int cbase = wg * W;
    int n = total - cbase;
    if (n > W) n = W;
    if (n < 0) n = 0;

    // stage this warp's pair chunk into smem (once; static schedule)
    const uint2* __restrict__ pbase;
    if (W <= SMEM_CAP) {
        uint2* mych = sh_pairs + wcta * SMEM_CAP;
        for (int j = lane; j < n; j += 32) mych[j] = g_pairs[cbase + j];
        __syncwarp();
        pbase = mych;
    } else {
        pbase = g_pairs + cbase;       // fallback (not expected)
    }

    // zero-init fp32 s(t=0) (mirror(t=0) never read: fill+phase1 skipped at t=0)
    for (int idx = blockIdx.x * MAIN_THREADS + threadIdx.x;
         idx < N_TOTAL * BATCH; idx += MAIN_BLOCKS * MAIN_THREADS)
        g_s0[idx] = 0.0f;
    grid_barrier();

    for (int t = 0; t < T_ITERS; ++t) {
        const float*  src  = (t & 1) ? g_s1  : g_s0;
        float*        dst  = (t & 1) ? g_s0  : g_s1;
        const __half* srcm = (t & 1) ? g_sm1 : g_sm0;
        __half*       dstm = (t & 1) ? g_sm0 : g_sm1;

        if (t > 0) {
            // ---- slab fill: 128 KB straight copy (mirror layout == slab) ----
            {
                const uint4* __restrict__ ms =
                    reinterpret_cast<const uint4*>(srcm + grp * (N_TOTAL * GB));
                uint4* md = reinterpret_cast<uint4*>(slab);
                #pragma unroll
                for (int r = 0; r < SLAB_BYTES / 16 / MAIN_THREADS; ++r) {
                    const int i = r * MAIN_THREADS + threadIdx.x;
                    md[i] = __ldcg(ms + i);
                }
            }
            __syncthreads();

            // ---- phase 1: balanced SpMM partials (all gathers from SMEM) ----
            int pos = 0;
            while (pos < n) {
                const unsigned h0 = pbase[pos].x;
                const int row = (int)(h0 >> 20);
                int run_end = g_row_start[row + 1] - cbase;
                if (run_end > n) run_end = n;
                const int slot = wg - g_row_w0[row];

                float a0 = 0.0f, a1 = 0.0f, a2 = 0.0f, a3 = 0.0f;
                for (int k = pos; k < run_end; k += 8) {
                    const int idx = k + p;
                    if (idx < run_end) {
                        const uint2 pr = pbase[idx];
                        const char* sp = slab + (pr.x & OFF_MASK) + q * 8;
                        const uint2 hv = *reinterpret_cast<const uint2*>(sp);
                        const float2 lo = __half22float2(
                            *reinterpret_cast<const __half2*>(&hv.x));
                        const float2 hi = __half22float2(
                            *reinterpret_cast<const __half2*>(&hv.y));
                        const float v = __uint_as_float(pr.y);
                        a0 = fmaf(v, lo.x, a0);
                        a1 = fmaf(v, lo.y, a1);
                        a2 = fmaf(v, hi.x, a2);
                        a3 = fmaf(v, hi.y, a3);
                    }
                }
                // reduce across nnz-octet positions (lane bits 2..4)
                #pragma unroll
                for (int d = 4; d < 32; d <<= 1) {
                    a0 += __shfl_xor_sync(0xffffffffu, a0, d);
                    a1 += __shfl_xor_sync(0xffffffffu, a1, d);
                    a2 += __shfl_xor_sync(0xffffffffu, a2, d);
                    a3 += __shfl_xor_sync(0xffffffffu, a3, d);
                }
                if (p == 0 && slot >= 0 && slot < NSLOTS) {
                    float4 vv = make_float4(a0, a1, a2, a3);
                    *reinterpret_cast<float4*>(
                        g_part + (((grp * N_MROWS + row) * NSLOTS) + slot) * GB
                               + q * 4) = vv;
                }
                pos = run_end;
            }
            grid_barrier();
        }

        // ---------- phase 2: combine + activation + state update ----------
        const float* __restrict__ nzT = g_noiseT + (size_t)t * (N_TOTAL * BATCH);
        const int node = gwarp;                       // 4736 warps >= 4096 nodes
        if (node < N_TOTAL) {
            const int nb = node * BATCH + lane;
            const int lg = lane >> 4;                 // group of this batch lane
            const int bb = lane & 15;
            float phi = 0.0f;
            if (node >= N_IN && t > 0) {
                const int r   = node - N_IN;
                const int nsl = g_row_nslots[r];
                const float* pp =
                    g_part + ((lg * N_MROWS + r) * NSLOTS) * GB + bb;
                #pragma unroll
                for (int sl = 0; sl < NSLOTS; ++sl)
                    if (sl < nsl) phi += pp[sl * GB];
            }
            phi += flux[node];
            if (node < N_IN) phi += g_xT[nb];
            phi += nzT[nb];
            phi = fminf(fmaxf(phi, -0.5f), 0.5f);
            const float phip = (phi >= 0.5f) ? -0.5f : phi;  // periodic wrap

            const float sold = src[nb];
            const float gact = tanhf(phip) * (1.0f - sold);
            float snew = sold + DT_C * (gamma[node] * gact - sold * g_inv_tau[node]);
            snew = fminf(fmaxf(snew, -1.0f), 1.0f);
            dst[nb] = snew;
            dstm[lg * (N_TOTAL * GB) + node * GB + bb] = __float2half_rn(snew);

            if (t == T_ITERS - 1 && node >= N_IN + N_HID)
                out[(size_t)lane * N_OUT + (node - (N_IN + N_HID))] = snew;
        }
        if (t != T_ITERS - 1) grid_barrier();
    }
}

// ---------------- launch: 4 launches, main at index 3 (ncu capture slot) ----
extern "C" void kernel_launch(void* const* d_in, const int* in_sizes, int n_in,
                              void* d_out, int out_size) {
    const float* x     = (const float*)d_in[0];   // [32, 1024]
    const float* J     = (const float*)d_in[1];   // [4096, 4096]
    const float* gamma = (const float*)d_in[2];   // [4096]
    const float* tau   = (const float*)d_in[3];   // [4096]
    const float* flux  = (const float*)d_in[4];   // [4096]
    const float* mask  = (const float*)d_in[5];   // [4096, 4096]
    const float* noise = (const float*)d_in[6];   // [100, 32, 4096]
    float* out = (float*)d_out;                   // [32, 128]
    (void)in_sizes; (void)n_in; (void)out_size;

    cudaFuncSetAttribute(soen_main_kernel,
                         cudaFuncAttributeMaxDynamicSharedMemorySize, SMEM_BYTES);

    prep_kernel<<<PREP_BLKS, dim3(32, 8)>>>(mask, tau, noise, x);      // idx 0
    scan_kernel<<<1, 1024>>>();                                        // idx 1
    fill_kernel<<<(N_MROWS * 32 + 255) / 256, 256>>>(J, mask);         // idx 2
    soen_main_kernel<<<MAIN_BLOCKS, MAIN_THREADS, SMEM_BYTES>>>(       // idx 3
        gamma, flux, out);
}

// round 14
// speedup vs baseline: 1.4155x; 1.0401x over previous
#include <cuda_runtime.h>
#include <cuda_fp16.h>
#include <cstdint>

// ---------------- problem constants ----------------
#define N_TOTAL   4096
#define N_IN      1024
#define N_HID     2944
#define N_OUT     128
#define N_MROWS   3072          // matrix rows: nodes 1024..4095
#define BATCH     32
#define T_ITERS   100
#define DT_C      0.05f

// ---------------- kernel config --------------------
#define MAIN_BLOCKS   148
#define MAIN_THREADS  1024
#define MAIN_WARPS    (MAIN_THREADS / 32)              // 32
#define NCLUST        37                               // row-ranges per group
#define CLW           64                               // warps per 2-CTA cluster

#define NGROUPS        2                               // batch groups of 16
#define GB             16                              // batches per group

#define MAX_NNZ   (2 * 1024 * 1024)                    // expected ~815k padded
#define SMEM_CAP  368                                  // pairs per warp in smem
#define SLAB_BYTES (N_TOTAL * GB * 2)                  // 128 KB fp16 state slab
#define PAIR_BYTES (MAIN_WARPS * SMEM_CAP * 8)         // 94.2 KB
#define SMEM_BYTES (SLAB_BYTES + PAIR_BYTES)           // 220 KB < 227 KB cap
#define NSLOTS    4                                    // max chunks spanning a row

// pair word0 layout: [31:20]=row (12b), [16:5]=col*32 byte offset (col<<5)
#define OFF_MASK  0x0001FFE0u

// prep mega-kernel block ranges (blockDim = 32x8 = 256)
#define PREP_NOISE_BLKS  ((N_TOTAL / 32) * T_ITERS)    // 12800
#define PREP_X_BLKS      (N_IN / 32)                   // 32
#define PREP_CNT_BLKS    (N_MROWS / 8)                 // 384
#define PREP_BLKS        (PREP_NOISE_BLKS + PREP_X_BLKS + PREP_CNT_BLKS)

#define CLUSTER_ARRIVE() asm volatile("barrier.cluster.arrive.aligned;" ::: "memory")
#define CLUSTER_WAIT()   asm volatile("barrier.cluster.wait.aligned;" ::: "memory")

// ---------------- device scratch (no allocs allowed) ----------------
__device__ __align__(16) uint2 g_pairs[MAX_NNZ];   // {row<<20|col<<5, f32 bits}
__device__ int  g_row_start[N_MROWS + 1];          // padded-even prefix
__device__ int  g_row_cnt[N_MROWS];                // padded (even) counts
__device__ int  g_row_w0[N_MROWS];                 // first cluster-warp covering row
__device__ int  g_row_nslots[N_MROWS];             // #chunks spanning row (0..4)
__device__ int  g_clu_row[NCLUST + 1];             // row-range boundaries
__device__ int  g_clu_base[NCLUST + 1];            // pair-index boundaries
__device__ int  g_clu_W[NCLUST];                   // per-cluster chunk size (even)

__device__ float g_part[NGROUPS * N_MROWS * NSLOTS * GB]; // [g][row][slot][16]
__device__ float g_s0[N_TOTAL * BATCH];            // fp32 state ping [node][batch]
__device__ float g_s1[N_TOTAL * BATCH];            // fp32 state pong
// fp16 mirrors, layout [g][node][16]: each group's slab is one contiguous 128KB
__device__ __align__(16) __half g_sm0[NGROUPS * N_TOTAL * GB];
__device__ __align__(16) __half g_sm1[NGROUPS * N_TOTAL * GB];
__device__ __half g_noiseT[(size_t)T_ITERS * N_TOTAL * BATCH]; // [t][node][b] fp16
__device__ float g_xT[N_IN * BATCH];               // [node][b]
__device__ float g_inv_tau[N_TOTAL];

// flag barrier state (no same-address atomics -> no L2-atom serialization)
__device__ volatile unsigned g_flags[MAIN_BLOCKS];
__device__ volatile unsigned g_bar_gen;

// ---------------- software grid barrier (flag-based) ----------------
// Arrival: thread0 __threadfence (emits CCTL.IVALL -> whole-SM L1D invalidate
// + publishes this CTA's writes), then STG its flag. CTA0's warp0 polls all
// flags (volatile, L1-bypassing) and releases g_bar_gen. No loads fill L1
// between the IVALL and the release, so post-barrier plain L1-cached loads of
// cross-SM data are safe (validated rounds 6-13).
__device__ __forceinline__ void grid_barrier() {
    __syncthreads();
    if (blockIdx.x == 0) {
        if (threadIdx.x < 32) {
            if (threadIdx.x == 0) __threadfence();
            const unsigned gen = g_bar_gen;
            bool done = false;
            while (!done) {
                bool ok = true;
                for (int i = threadIdx.x; i < MAIN_BLOCKS; i += 32)
                    ok &= (i == 0) || (g_flags[i] == gen + 1u);
                done = __all_sync(0xffffffffu, ok);
            }
            if (threadIdx.x == 0) g_bar_gen = gen + 1u;
        }
        __syncthreads();
    } else {
        if (threadIdx.x == 0) {
            __threadfence();
            const unsigned gen = g_bar_gen;
            g_flags[blockIdx.x] = gen + 1u;
            while (g_bar_gen == gen) { }
        }
        __syncthreads();
    }
}

// ---------------- L0: mega-prep (transposes + counts + inv_tau) ----------------
__global__ void prep_kernel(const float* __restrict__ mask,
                            const float* __restrict__ tau,
                            const float* __restrict__ noise,
                            const float* __restrict__ x) {
    __shared__ float tile[32][33];
    const unsigned blk = blockIdx.x;

    if (blk < PREP_NOISE_BLKS) {                   // noise transpose -> fp16
        const int t  = blk >> 7;                   // /128
        const int i0 = (blk & 127) * 32;
        for (int bb = threadIdx.y; bb < 32; bb += 8)
            tile[bb][threadIdx.x] =
                noise[((size_t)t * BATCH + bb) * N_TOTAL + i0 + threadIdx.x];
        __syncthreads();
        for (int ii = threadIdx.y; ii < 32; ii += 8)
            g_noiseT[((size_t)t * N_TOTAL + i0 + ii) * BATCH + threadIdx.x] =
                __float2half_rn(tile[threadIdx.x][ii]);
        return;
    }
    if (blk < PREP_NOISE_BLKS + PREP_X_BLKS) {
        const int xb = blk - PREP_NOISE_BLKS;
        const int i0 = xb * 32;
        for (int bb = threadIdx.y; bb < 32; bb += 8)
            tile[bb][threadIdx.x] = x[(size_t)bb * N_IN + i0 + threadIdx.x];
        __syncthreads();
        for (int ii = threadIdx.y; ii < 32; ii += 8)
            g_xT[(i0 + ii) * BATCH + threadIdx.x] = tile[threadIdx.x][ii];
        const int gt = xb * 256 + threadIdx.y * 32 + threadIdx.x;
        if (gt < N_TOTAL) g_inv_tau[gt] = 1.0f / tau[gt];
        return;
    }
    // row counts: warp per matrix row
    const int warp = (blk - PREP_NOISE_BLKS - PREP_X_BLKS) * 8 + threadIdx.y;
    const int lane = threadIdx.x;
    if (warp >= N_MROWS) return;
    const float* __restrict__ mrow = mask + (size_t)(N_IN + warp) * N_TOTAL;
    int cnt = 0;
    for (int j = lane; j < N_TOTAL; j += 32) {
        unsigned b = __ballot_sync(0xffffffffu, mrow[j] != 0.0f);
        cnt += __popc(b);
    }
    if (lane == 0) g_row_cnt[warp] = (cnt + 1) & ~1;   // pad to even
}

// ---------------- L1: prefix over padded counts + cluster row ranges ----------
__global__ void scan_kernel() {
    __shared__ int sh[32];
    const int t = threadIdx.x;      // 1024 threads
    int off = 0;
    for (int seg = 0; seg < 3; ++seg) {
        int v = g_row_cnt[seg * 1024 + t];
        int xv = v;
        #pragma unroll
        for (int d = 1; d < 32; d <<= 1) {
            int y = __shfl_up_sync(0xffffffffu, xv, d);
            if ((t & 31) >= d) xv += y;
        }
        if ((t & 31) == 31) sh[t >> 5] = xv;
        __syncthreads();
        if (t < 32) {
            int x2 = sh[t];
            #pragma unroll
            for (int d = 1; d < 32; d <<= 1) {
                int y = __shfl_up_sync(0xffffffffu, x2, d);
                if (t >= d) x2 += y;
            }
            sh[t] = x2;
        }
        __syncthreads();
        const int incl = xv + ((t >= 32) ? sh[(t >> 5) - 1] : 0);
        g_row_start[seg * 1024 + t] = off + incl - v;
        const int segtotal = sh[31];
        __syncthreads();
        off += segtotal;
    }
    const int total = off;                  // uniform across threads
    if (t == 0) g_row_start[N_MROWS] = total;
    __syncthreads();

    // cluster row boundaries: 37 weight-balanced contiguous ranges
    if (t <= NCLUST) {
        int r;
        if (t == 0) r = 0;
        else if (t == NCLUST) r = N_MROWS;
        else {
            const long long target = (long long)t * total / NCLUST;
            int lo = 0, hi = N_MROWS;       // smallest r with start[r] >= target
            while (lo < hi) {
                const int mid = (lo + hi) >> 1;
                if (g_row_start[mid] >= target) hi = mid; else lo = mid + 1;
            }
            r = lo;
        }
        g_clu_row[t]  = r;
        g_clu_base[t] = g_row_start[r];
    }
    __syncthreads();
    if (t < NCLUST) {
        const int diff = g_clu_base[t + 1] - g_clu_base[t];
        int w = (diff + CLW - 1) / CLW;
        w = (w + 1) & ~1;
        if (w < 2) w = 2;
        g_clu_W[t] = w;
    }
}

// ---------------- L2: fill flat pair array + per-row chunk metadata ----------------
__global__ void fill_kernel(const float* __restrict__ J,
                            const float* __restrict__ mask) {
    const int warp = (blockIdx.x * blockDim.x + threadIdx.x) >> 5;
    const int lane = threadIdx.x & 31;
    if (warp >= N_MROWS) return;
    const int row = N_IN + warp;
    const float* __restrict__ mrow = mask + (size_t)row * N_TOTAL;
    const float* __restrict__ jrow = J    + (size_t)row * N_TOTAL;
    const int base = g_row_start[warp];
    const unsigned rtag = (unsigned)warp << 20;

    int pos = base;
    for (int j = lane; j < N_TOTAL; j += 32) {
        const float mv = mrow[j];
        const bool  nz = (mv != 0.0f);
        unsigned b = __ballot_sync(0xffffffffu, nz);
        if (nz) {
            int idx = pos + __popc(b & ((1u << lane) - 1u));
            g_pairs[idx] = make_uint2(rtag | ((unsigned)j << 5),
                                      __float_as_uint(jrow[j] * mv));
        }
        pos += __popc(b);
    }
    const int cnt = pos - base;
    if (lane == 0) {
        if (cnt & 1) g_pairs[base + cnt] = make_uint2(rtag, 0u);  // pad, val=0
        const int cnt_pad = (cnt + 1) & ~1;
        int k = 0;
        while (k < NCLUST - 1 && base >= g_clu_base[k + 1]) ++k;
        const int Wk = g_clu_W[k];
        int w0 = 0, nsl = 0;
        if (cnt_pad > 0) {
            w0  = (base - g_clu_base[k]) / Wk;
            nsl = (base + cnt_pad - 1 - g_clu_base[k]) / Wk - w0 + 1;
            if (nsl > NSLOTS) nsl = NSLOTS;
        }
        g_row_w0[warp]     = w0;
        g_row_nslots[warp] = nsl;
    }
}

// ---------------- L3: main persistent recurrence kernel ----------------
// Grid 148, cluster (2,1,1): cluster c owns batch-group g=c&1 and row range
// k=c>>1 of 37 weight-balanced contiguous ranges. CTA keeps its group's fp16
// state slab [4096][16] (128 KB smem), refilled per iter from the mirror.
// Phase1: cluster-warp wic owns pairs [base_k + wic*Wk, +Wk). Lane map
//   (p=lane>>1 16 nnz, q=lane&1 batch-octet): one LDS.128 gathers 8 fp16
//   batches -> 16 nnz per warp instruction. fp32 accumulate (8 regs); reduce
//   over p via 4 shfl_xor; lanes p==0 store float4 partials.
// Input-node updates (no partials needed) run before the cluster barrier.
// barrier.cluster (arrive=cluster-scope release + CCTL.IVALL) replaces the
// global combine barrier; phase2 updates the cluster's rows for its group.
// One global flag-barrier per iteration publishes mirrors for the next fill.
__global__ void __launch_bounds__(MAIN_THREADS, 1)
soen_main_kernel(const float* __restrict__ gamma,
                 const float* __restrict__ flux,
                 float* __restrict__ out) {
    extern __shared__ char smem_raw[];
    char*  slab     = smem_raw;                        // 128 KB fp16 state
    uint2* sh_pairs = (uint2*)(smem_raw + SLAB_BYTES); // pair chunks

    const int lane = threadIdx.x & 31;
    const int wcta = threadIdx.x >> 5;
    const int cid  = blockIdx.x >> 1;                  // cluster 0..73
    const int grp  = cid & 1;                          // batch group
    const int kcl  = cid >> 1;                         // row-range 0..36
    const int wic  = (blockIdx.x & 1) * 32 + wcta;     // warp-in-cluster 0..63
    const int p    = lane >> 1;                        // nnz position 0..15
    const int q    = lane & 1;                         // batch octet 0..1

    const int Wk    = g_clu_W[kcl];
    const int cb    = g_clu_base[kcl];
    const int cend  = g_clu_base[kcl + 1];
    const int cbase = cb + wic * Wk;
    int n = cend - cbase;
    if (n > Wk) n = Wk;
    if (n < 0) n = 0;

    // stage this warp's pair chunk into smem (once; static schedule)
    const uint2* __restrict__ pbase;
    if (Wk <= SMEM_CAP) {
        uint2* mych = sh_pairs + wcta * SMEM_CAP;
        for (int j = lane; j < n; j += 32) mych[j] = g_pairs[cbase + j];
        __syncwarp();
        pbase = mych;
    } else {
        pbase = g_pairs + cbase;       // fallback (not expected)
    }

    // zero-init fp32 s(t=0)
    for (int idx = blockIdx.x * MAIN_THREADS + threadIdx.x;
         idx < N_TOTAL * BATCH; idx += MAIN_BLOCKS * MAIN_THREADS)
        g_s0[idx] = 0.0f;
    grid_barrier();

    const int r_lo = g_clu_row[kcl];
    const int r_hi = g_clu_row[kcl + 1];
    const int gw   = kcl * CLW + wic;                  // group-warp id (input map)

    for (int t = 0; t < T_ITERS; ++t) {
        const float*  src  = (t & 1) ? g_s1  : g_s0;
        float*        dst  = (t & 1) ? g_s0  : g_s1;
        const __half* srcm = (t & 1) ? g_sm1 : g_sm0;
        __half*       dstm = (t & 1) ? g_sm0 : g_sm1;
        const __half* __restrict__ nzT = g_noiseT + (size_t)t * (N_TOTAL * BATCH);

        if (t > 0) {
            // ---- slab fill: 128 KB straight copy (mirror layout == slab) ----
            {
                const uint4* __restrict__ ms =
                    reinterpret_cast<const uint4*>(srcm + grp * (N_TOTAL * GB));
                uint4* md = reinterpret_cast<uint4*>(slab);
                #pragma unroll
                for (int r = 0; r < SLAB_BYTES / 16 / MAIN_THREADS; ++r) {
                    const int i = r * MAIN_THREADS + threadIdx.x;
                    md[i] = __ldcg(ms + i);
                }
            }
            __syncthreads();

            // ---- phase 1: balanced SpMM partials (all gathers from SMEM) ----
            int pos = 0;
            while (pos < n) {
                const unsigned h0 = pbase[pos].x;
                const int row = (int)(h0 >> 20);
                int run_end = g_row_start[row + 1] - cbase;
                if (run_end > n) run_end = n;
                const int slot = wic - g_row_w0[row];

                float a0 = 0.f, a1 = 0.f, a2 = 0.f, a3 = 0.f;
                float a4 = 0.f, a5 = 0.f, a6 = 0.f, a7 = 0.f;
                for (int kk = pos; kk < run_end; kk += 16) {
                    const int idx = kk + p;
                    if (idx < run_end) {
                        const uint2 pr = pbase[idx];
                        const uint4 hv = *reinterpret_cast<const uint4*>(
                            slab + (pr.x & OFF_MASK) + q * 16);
                        const float2 f0 = __half22float2(
                            *reinterpret_cast<const __half2*>(&hv.x));
                        const float2 f1 = __half22float2(
                            *reinterpret_cast<const __half2*>(&hv.y));
                        const float2 f2 = __half22float2(
                            *reinterpret_cast<const __half2*>(&hv.z));
                        const float2 f3 = __half22float2(
                            *reinterpret_cast<const __half2*>(&hv.w));
                        const float v = __uint_as_float(pr.y);
                        a0 = fmaf(v, f0.x, a0);  a1 = fmaf(v, f0.y, a1);
                        a2 = fmaf(v, f1.x, a2);  a3 = fmaf(v, f1.y, a3);
                        a4 = fmaf(v, f2.x, a4);  a5 = fmaf(v, f2.y, a5);
                        a6 = fmaf(v, f3.x, a6);  a7 = fmaf(v, f3.y, a7);
                    }
                }
                // reduce across nnz positions (lane bits 1..4)
                #pragma unroll
                for (int d = 2; d < 32; d <<= 1) {
                    a0 += __shfl_xor_sync(0xffffffffu, a0, d);
                    a1 += __shfl_xor_sync(0xffffffffu, a1, d);
                    a2 += __shfl_xor_sync(0xffffffffu, a2, d);
                    a3 += __shfl_xor_sync(0xffffffffu, a3, d);
                    a4 += __shfl_xor_sync(0xffffffffu, a4, d);
                    a5 += __shfl_xor_sync(0xffffffffu, a5, d);
                    a6 += __shfl_xor_sync(0xffffffffu, a6, d);
                    a7 += __shfl_xor_sync(0xffffffffu, a7, d);
                }
                if (p == 0 && slot >= 0 && slot < NSLOTS) {
                    float* pb2 = g_part +
                        (((grp * N_MROWS + row) * NSLOTS) + slot) * GB + q * 8;
                    *reinterpret_cast<float4*>(pb2)     = make_float4(a0, a1, a2, a3);
                    *reinterpret_cast<float4*>(pb2 + 4) = make_float4(a4, a5, a6, a7);
                }
                pos = run_end;
            }
        }

        // ---- input-node updates (no partials needed; before cluster sync) ----
        if (gw < N_IN && lane < GB) {
            const int node = gw;
            const int b    = grp * GB + lane;
            const int nb   = node * BATCH + b;
            float phi = flux[node] + g_xT[nb] + __half2float(nzT[nb]);
            phi = fminf(fmaxf(phi, -0.5f), 0.5f);
            const float phip = (phi >= 0.5f) ? -0.5f : phi;
            const float sold = src[nb];
            const float gact = tanhf(phip) * (1.0f - sold);
            float snew = sold + DT_C * (gamma[node] * gact - sold * g_inv_tau[node]);
            snew = fminf(fmaxf(snew, -1.0f), 1.0f);
            dst[nb] = snew;
            dstm[grp * (N_TOTAL * GB) + node * GB + lane] = __float2half_rn(snew);
        }

        if (t > 0) {                  // partial visibility within cluster
            CLUSTER_ARRIVE();
            CLUSTER_WAIT();
        }

        // ---- phase 2: cluster's rows, this group's 16 batches ----
        const int bb = lane & 15;
        for (int ri = r_lo + wic * 2 + (lane >> 4); ri < r_hi; ri += 2 * CLW) {
            const int node = N_IN + ri;
            const int b    = grp * GB + bb;
            const int nb   = node * BATCH + b;
            float phi = 0.0f;
            if (t > 0) {
                const int nsl = g_row_nslots[ri];
                const float* pp =
                    g_part + ((grp * N_MROWS + ri) * NSLOTS) * GB + bb;
                #pragma unroll
                for (int sl = 0; sl < NSLOTS; ++sl)
                    if (sl < nsl) phi += pp[sl * GB];
            }
            phi += flux[node] + __half2float(nzT[nb]);
            phi = fminf(fmaxf(phi, -0.5f), 0.5f);
            const float phip = (phi >= 0.5f) ? -0.5f : phi;  // periodic wrap

            const float sold = src[nb];
            const float gact = tanhf(phip) * (1.0f - sold);
            float snew = sold + DT_C * (gamma[node] * gact - sold * g_inv_tau[node]);
            snew = fminf(fmaxf(snew, -1.0f), 1.0f);
            dst[nb] = snew;
            dstm[grp * (N_TOTAL * GB) + node * GB + bb] = __float2half_rn(snew);

            if (t == T_ITERS - 1 && node >= N_IN + N_HID)
                out[(size_t)b * N_OUT + (node - (N_IN + N_HID))] = snew;
        }
        if (t != T_ITERS - 1) grid_barrier();
    }
}

// ---------------- launch: 4 launches, main at index 3 (ncu capture slot) ----
extern "C" void kernel_launch(void* const* d_in, const int* in_sizes, int n_in,
                              void* d_out, int out_size) {
    const float* x     = (const float*)d_in[0];   // [32, 1024]
    const float* J     = (const float*)d_in[1];   // [4096, 4096]
    const float* gamma = (const float*)d_in[2];   // [4096]
    const float* tau   = (const float*)d_in[3];   // [4096]
    const float* flux  = (const float*)d_in[4];   // [4096]
    const float* mask  = (const float*)d_in[5];   // [4096, 4096]
    const float* noise = (const float*)d_in[6];   // [100, 32, 4096]
    float* out = (float*)d_out;                   // [32, 128]
    (void)in_sizes; (void)n_in; (void)out_size;

    cudaFuncSetAttribute(soen_main_kernel,
                         cudaFuncAttributeMaxDynamicSharedMemorySize, SMEM_BYTES);

    prep_kernel<<<PREP_BLKS, dim3(32, 8)>>>(mask, tau, noise, x);      // idx 0
    scan_kernel<<<1, 1024>>>();                                        // idx 1
    fill_kernel<<<(N_MROWS * 32 + 255) / 256, 256>>>(J, mask);         // idx 2

    cudaLaunchConfig_t cfg = {};                                       // idx 3
    cfg.gridDim  = dim3(MAIN_BLOCKS, 1, 1);
    cfg.blockDim = dim3(MAIN_THREADS, 1, 1);
    cfg.dynamicSmemBytes = SMEM_BYTES;
    cudaLaunchAttribute attrs[1];
    attrs[0].id = cudaLaunchAttributeClusterDimension;
    attrs[0].val.clusterDim = {2, 1, 1};
    cfg.attrs = attrs;
    cfg.numAttrs = 1;
    cudaLaunchKernelEx(&cfg, soen_main_kernel, gamma, flux, out);
}

// round 15
// speedup vs baseline: 1.4314x; 1.0113x over previous
#include <cuda_runtime.h>
#include <cuda_fp16.h>
#include <cstdint>

// ---------------- problem constants ----------------
#define N_TOTAL   4096
#define N_IN      1024
#define N_HID     2944
#define N_OUT     128
#define N_MROWS   3072          // matrix rows: nodes 1024..4095
#define BATCH     32
#define T_ITERS   100
#define DT_C      0.05f

// ---------------- kernel config --------------------
#define MAIN_BLOCKS   148
#define MAIN_THREADS  1024
#define MAIN_WARPS    (MAIN_THREADS / 32)              // 32
#define NCLUST        37                               // row-ranges per group
#define CLW           64                               // warps per 2-CTA cluster

#define NGROUPS        2                               // batch groups of 16
#define GB             16                              // batches per group

#define MAX_NNZ   (2 * 1024 * 1024)                    // expected ~815k padded
#define SMEM_CAP  368                                  // pairs per warp in smem
#define SLAB_BYTES (N_TOTAL * GB * 2)                  // 128 KB fp16 state slab
#define PAIR_BYTES (MAIN_WARPS * SMEM_CAP * 8)         // 94.2 KB
#define SMEM_BYTES (SLAB_BYTES + PAIR_BYTES)           // 220 KB < 227 KB cap
#define NSLOTS    4                                    // max chunks spanning a row

// pair word0 layout: [31:20]=row (12b), [16:5]=col*32 byte offset (col<<5)
// pair word1: J value as DUPLICATED half2 (both halves = J)
#define OFF_MASK  0x0001FFE0u

// prep mega-kernel block ranges (blockDim = 32x8 = 256)
#define PREP_NOISE_BLKS  ((N_TOTAL / 32) * T_ITERS)    // 12800
#define PREP_X_BLKS      (N_IN / 32)                   // 32
#define PREP_CNT_BLKS    (N_MROWS / 8)                 // 384
#define PREP_BLKS        (PREP_NOISE_BLKS + PREP_X_BLKS + PREP_CNT_BLKS)

#define CLUSTER_ARRIVE() asm volatile("barrier.cluster.arrive.aligned;" ::: "memory")
#define CLUSTER_WAIT()   asm volatile("barrier.cluster.wait.aligned;" ::: "memory")

// ---------------- device scratch (no allocs allowed) ----------------
__device__ __align__(16) uint2 g_pairs[MAX_NNZ];   // {row<<20|col<<5, half2 J}
__device__ int  g_row_start[N_MROWS + 1];          // padded-even prefix
__device__ int  g_row_cnt[N_MROWS];                // padded (even) counts
__device__ int  g_row_w0[N_MROWS];                 // first cluster-warp covering row
__device__ int  g_row_nslots[N_MROWS];             // #chunks spanning row (0..4)
__device__ int  g_clu_row[NCLUST + 1];             // row-range boundaries
__device__ int  g_clu_base[NCLUST + 1];            // pair-index boundaries
__device__ int  g_clu_W[NCLUST];                   // per-cluster chunk size (even)

__device__ float g_part[NGROUPS * N_MROWS * NSLOTS * GB]; // [g][row][slot][16]
__device__ float g_s0[N_TOTAL * BATCH];            // fp32 state ping [node][batch]
__device__ float g_s1[N_TOTAL * BATCH];            // fp32 state pong
// fp16 mirrors, layout [g][node][16]: each group's slab is one contiguous 128KB
__device__ __align__(16) __half g_sm0[NGROUPS * N_TOTAL * GB];
__device__ __align__(16) __half g_sm1[NGROUPS * N_TOTAL * GB];
__device__ __half g_noiseT[(size_t)T_ITERS * N_TOTAL * BATCH]; // [t][node][b] fp16
__device__ float g_xT[N_IN * BATCH];               // [node][b]
__device__ float g_inv_tau[N_TOTAL];

// flag barrier state (no same-address atomics -> no L2-atom serialization)
__device__ volatile unsigned g_flags[MAIN_BLOCKS];
__device__ volatile unsigned g_bar_gen;

// ---------------- software grid barrier (flag-based) ----------------
// Arrival: thread0 __threadfence (emits CCTL.IVALL -> whole-SM L1D invalidate
// + publishes this CTA's writes), then STG its flag. CTA0's warp0 polls all
// flags (volatile, L1-bypassing) and releases g_bar_gen. No loads fill L1
// between the IVALL and the release, so post-barrier plain L1-cached loads of
// cross-SM data are safe (validated rounds 6-14).
__device__ __forceinline__ void grid_barrier() {
    __syncthreads();
    if (blockIdx.x == 0) {
        if (threadIdx.x < 32) {
            if (threadIdx.x == 0) __threadfence();
            const unsigned gen = g_bar_gen;
            bool done = false;
            while (!done) {
                bool ok = true;
                for (int i = threadIdx.x; i < MAIN_BLOCKS; i += 32)
                    ok &= (i == 0) || (g_flags[i] == gen + 1u);
                done = __all_sync(0xffffffffu, ok);
            }
            if (threadIdx.x == 0) g_bar_gen = gen + 1u;
        }
        __syncthreads();
    } else {
        if (threadIdx.x == 0) {
            __threadfence();
            const unsigned gen = g_bar_gen;
            g_flags[blockIdx.x] = gen + 1u;
            while (g_bar_gen == gen) { }
        }
        __syncthreads();
    }
}

// ---------------- L0: mega-prep (transposes + counts + inv_tau) ----------------
__global__ void prep_kernel(const float* __restrict__ mask,
                            const float* __restrict__ tau,
                            const float* __restrict__ noise,
                            const float* __restrict__ x) {
    __shared__ float tile[32][33];
    const unsigned blk = blockIdx.x;

    if (blk < PREP_NOISE_BLKS) {                   // noise transpose -> fp16
        const int t  = blk >> 7;                   // /128
        const int i0 = (blk & 127) * 32;
        for (int bb = threadIdx.y; bb < 32; bb += 8)
            tile[bb][threadIdx.x] =
                noise[((size_t)t * BATCH + bb) * N_TOTAL + i0 + threadIdx.x];
        __syncthreads();
        for (int ii = threadIdx.y; ii < 32; ii += 8)
            g_noiseT[((size_t)t * N_TOTAL + i0 + ii) * BATCH + threadIdx.x] =
                __float2half_rn(tile[threadIdx.x][ii]);
        return;
    }
    if (blk < PREP_NOISE_BLKS + PREP_X_BLKS) {
        const int xb = blk - PREP_NOISE_BLKS;
        const int i0 = xb * 32;
        for (int bb = threadIdx.y; bb < 32; bb += 8)
            tile[bb][threadIdx.x] = x[(size_t)bb * N_IN + i0 + threadIdx.x];
        __syncthreads();
        for (int ii = threadIdx.y; ii < 32; ii += 8)
            g_xT[(i0 + ii) * BATCH + threadIdx.x] = tile[threadIdx.x][ii];
        const int gt = xb * 256 + threadIdx.y * 32 + threadIdx.x;
        if (gt < N_TOTAL) g_inv_tau[gt] = 1.0f / tau[gt];
        return;
    }
    // row counts: warp per matrix row
    const int warp = (blk - PREP_NOISE_BLKS - PREP_X_BLKS) * 8 + threadIdx.y;
    const int lane = threadIdx.x;
    if (warp >= N_MROWS) return;
    const float* __restrict__ mrow = mask + (size_t)(N_IN + warp) * N_TOTAL;
    int cnt = 0;
    for (int j = lane; j < N_TOTAL; j += 32) {
        unsigned b = __ballot_sync(0xffffffffu, mrow[j] != 0.0f);
        cnt += __popc(b);
    }
    if (lane == 0) g_row_cnt[warp] = (cnt + 1) & ~1;   // pad to even
}

// ---------------- L1: prefix over padded counts + cluster row ranges ----------
__global__ void scan_kernel() {
    __shared__ int sh[32];
    const int t = threadIdx.x;      // 1024 threads
    int off = 0;
    for (int seg = 0; seg < 3; ++seg) {
        int v = g_row_cnt[seg * 1024 + t];
        int xv = v;
        #pragma unroll
        for (int d = 1; d < 32; d <<= 1) {
            int y = __shfl_up_sync(0xffffffffu, xv, d);
            if ((t & 31) >= d) xv += y;
        }
        if ((t & 31) == 31) sh[t >> 5] = xv;
        __syncthreads();
        if (t < 32) {
            int x2 = sh[t];
            #pragma unroll
            for (int d = 1; d < 32; d <<= 1) {
                int y = __shfl_up_sync(0xffffffffu, x2, d);
                if (t >= d) x2 += y;
            }
            sh[t] = x2;
        }
        __syncthreads();
        const int incl = xv + ((t >= 32) ? sh[(t >> 5) - 1] : 0);
        g_row_start[seg * 1024 + t] = off + incl - v;
        const int segtotal = sh[31];
        __syncthreads();
        off += segtotal;
    }
    const int total = off;                  // uniform across threads
    if (t == 0) g_row_start[N_MROWS] = total;
    __syncthreads();

    // cluster row boundaries: 37 weight-balanced contiguous ranges
    if (t <= NCLUST) {
        int r;
        if (t == 0) r = 0;
        else if (t == NCLUST) r = N_MROWS;
        else {
            const long long target = (long long)t * total / NCLUST;
            int lo = 0, hi = N_MROWS;       // smallest r with start[r] >= target
            while (lo < hi) {
                const int mid = (lo + hi) >> 1;
                if (g_row_start[mid] >= target) hi = mid; else lo = mid + 1;
            }
            r = lo;
        }
        g_clu_row[t]  = r;
        g_clu_base[t] = g_row_start[r];
    }
    __syncthreads();
    if (t < NCLUST) {
        const int diff = g_clu_base[t + 1] - g_clu_base[t];
        int w = (diff + CLW - 1) / CLW;
        w = (w + 1) & ~1;
        if (w < 2) w = 2;
        g_clu_W[t] = w;
    }
}

// ---------------- L2: fill flat pair array + per-row chunk metadata ----------------
__global__ void fill_kernel(const float* __restrict__ J,
                            const float* __restrict__ mask) {
    const int warp = (blockIdx.x * blockDim.x + threadIdx.x) >> 5;
    const int lane = threadIdx.x & 31;
    if (warp >= N_MROWS) return;
    const int row = N_IN + warp;
    const float* __restrict__ mrow = mask + (size_t)row * N_TOTAL;
    const float* __restrict__ jrow = J    + (size_t)row * N_TOTAL;
    const int base = g_row_start[warp];
    const unsigned rtag = (unsigned)warp << 20;

    int pos = base;
    for (int j = lane; j < N_TOTAL; j += 32) {
        const float mv = mrow[j];
        const bool  nz = (mv != 0.0f);
        unsigned b = __ballot_sync(0xffffffffu, nz);
        if (nz) {
            int idx = pos + __popc(b & ((1u << lane) - 1u));
            __half2 h2 = __float2half2_rn(jrow[j] * mv);   // duplicated fp16 J
            g_pairs[idx] = make_uint2(rtag | ((unsigned)j << 5),
                                      *reinterpret_cast<unsigned*>(&h2));
        }
        pos += __popc(b);
    }
    const int cnt = pos - base;
    if (lane == 0) {
        if (cnt & 1) g_pairs[base + cnt] = make_uint2(rtag, 0u);  // pad, val=0
        const int cnt_pad = (cnt + 1) & ~1;
        int k = 0;
        while (k < NCLUST - 1 && base >= g_clu_base[k + 1]) ++k;
        const int Wk = g_clu_W[k];
        int w0 = 0, nsl = 0;
        if (cnt_pad > 0) {
            w0  = (base - g_clu_base[k]) / Wk;
            nsl = (base + cnt_pad - 1 - g_clu_base[k]) / Wk - w0 + 1;
            if (nsl > NSLOTS) nsl = NSLOTS;
        }
        g_row_w0[warp]     = w0;
        g_row_nslots[warp] = nsl;
    }
}

// ---------------- L3: main persistent recurrence kernel ----------------
// Grid 148, cluster (2,1,1): cluster c owns batch-group g=c&1 and row range
// k=c>>1 of 37 weight-balanced contiguous ranges. CTA keeps its group's fp16
// state slab [4096][16] (128 KB smem), refilled per iter from the mirror.
// Phase1: cluster-warp wic owns pairs [base_k + wic*Wk, +Wk). Lane map
//   (p=lane>>1 16 nnz, q=lane&1 batch-octet): one LDS.128 gathers 8 fp16
//   batches; J is a duplicated half2 -> 4 HFMA2 per step (fp16 accumulate,
//   per-lane runs are short so rounding stays ~1e-4). Converted to fp32 per
//   row-run, reduced across p via shfl in fp32; lanes p==0 store partials.
// Input-node updates run before the cluster barrier; barrier.cluster makes
// partials visible; phase2 combines + updates; one global flag-barrier per
// iteration publishes mirrors for the next fill.
__global__ void __launch_bounds__(MAIN_THREADS, 1)
soen_main_kernel(const float* __restrict__ gamma,
                 const float* __restrict__ flux,
                 float* __restrict__ out) {
    extern __shared__ char smem_raw[];
    char*  slab     = smem_raw;                        // 128 KB fp16 state
    uint2* sh_pairs = (uint2*)(smem_raw + SLAB_BYTES); // pair chunks

    const int lane = threadIdx.x & 31;
    const int wcta = threadIdx.x >> 5;
    const int cid  = blockIdx.x >> 1;                  // cluster 0..73
    const int grp  = cid & 1;                          // batch group
    const int kcl  = cid >> 1;                         // row-range 0..36
    const int wic  = (blockIdx.x & 1) * 32 + wcta;     // warp-in-cluster 0..63
    const int p    = lane >> 1;                        // nnz position 0..15
    const int q    = lane & 1;                         // batch octet 0..1

    const int Wk    = g_clu_W[kcl];
    const int cb    = g_clu_base[kcl];
    const int cend  = g_clu_base[kcl + 1];
    const int cbase = cb + wic * Wk;
    int n = cend - cbase;
    if (n > Wk) n = Wk;
    if (n < 0) n = 0;

    // stage this warp's pair chunk into smem (once; static schedule)
    const uint2* __restrict__ pbase;
    if (Wk <= SMEM_CAP) {
        uint2* mych = sh_pairs + wcta * SMEM_CAP;
        for (int j = lane; j < n; j += 32) mych[j] = g_pairs[cbase + j];
        __syncwarp();
        pbase = mych;
    } else {
        pbase = g_pairs + cbase;       // fallback (not expected)
    }

    // zero-init fp32 s(t=0)
    for (int idx = blockIdx.x * MAIN_THREADS + threadIdx.x;
         idx < N_TOTAL * BATCH; idx += MAIN_BLOCKS * MAIN_THREADS)
        g_s0[idx] = 0.0f;
    grid_barrier();

    const int r_lo = g_clu_row[kcl];
    const int r_hi = g_clu_row[kcl + 1];
    const int gw   = kcl * CLW + wic;                  // group-warp id (input map)

    for (int t = 0; t < T_ITERS; ++t) {
        const float*  src  = (t & 1) ? g_s1  : g_s0;
        float*        dst  = (t & 1) ? g_s0  : g_s1;
        const __half* srcm = (t & 1) ? g_sm1 : g_sm0;
        __half*       dstm = (t & 1) ? g_sm0 : g_sm1;
        const __half* __restrict__ nzT = g_noiseT + (size_t)t * (N_TOTAL * BATCH);

        if (t > 0) {
            // ---- slab fill: 128 KB straight copy (mirror layout == slab) ----
            {
                const uint4* __restrict__ ms =
                    reinterpret_cast<const uint4*>(srcm + grp * (N_TOTAL * GB));
                uint4* md = reinterpret_cast<uint4*>(slab);
                #pragma unroll
                for (int r = 0; r < SLAB_BYTES / 16 / MAIN_THREADS; ++r) {
                    const int i = r * MAIN_THREADS + threadIdx.x;
                    md[i] = __ldcg(ms + i);
                }
            }
            __syncthreads();

            // ---- phase 1: balanced SpMM partials (HFMA2 on SMEM gathers) ----
            int pos = 0;
            while (pos < n) {
                const unsigned h0 = pbase[pos].x;
                const int row = (int)(h0 >> 20);
                int run_end = g_row_start[row + 1] - cbase;
                if (run_end > n) run_end = n;
                const int slot = wic - g_row_w0[row];

                __half2 c0 = __float2half2_rn(0.0f);
                __half2 c1 = c0, c2 = c0, c3 = c0;
                for (int kk = pos; kk < run_end; kk += 16) {
                    const int idx = kk + p;
                    if (idx < run_end) {
                        const uint2 pr = pbase[idx];
                        const uint4 hv = *reinterpret_cast<const uint4*>(
                            slab + (pr.x & OFF_MASK) + q * 16);
                        const __half2 jv = *reinterpret_cast<const __half2*>(&pr.y);
                        c0 = __hfma2(jv, *reinterpret_cast<const __half2*>(&hv.x), c0);
                        c1 = __hfma2(jv, *reinterpret_cast<const __half2*>(&hv.y), c1);
                        c2 = __hfma2(jv, *reinterpret_cast<const __half2*>(&hv.z), c2);
                        c3 = __hfma2(jv, *reinterpret_cast<const __half2*>(&hv.w), c3);
                    }
                }
                const float2 f0 = __half22float2(c0);
                const float2 f1 = __half22float2(c1);
                const float2 f2 = __half22float2(c2);
                const float2 f3 = __half22float2(c3);
                float a0 = f0.x, a1 = f0.y, a2 = f1.x, a3 = f1.y;
                float a4 = f2.x, a5 = f2.y, a6 = f3.x, a7 = f3.y;
                // reduce across nnz positions (lane bits 1..4) in fp32
                #pragma unroll
                for (int d = 2; d < 32; d <<= 1) {
                    a0 += __shfl_xor_sync(0xffffffffu, a0, d);
                    a1 += __shfl_xor_sync(0xffffffffu, a1, d);
                    a2 += __shfl_xor_sync(0xffffffffu, a2, d);
                    a3 += __shfl_xor_sync(0xffffffffu, a3, d);
                    a4 += __shfl_xor_sync(0xffffffffu, a4, d);
                    a5 += __shfl_xor_sync(0xffffffffu, a5, d);
                    a6 += __shfl_xor_sync(0xffffffffu, a6, d);
                    a7 += __shfl_xor_sync(0xffffffffu, a7, d);
                }
                if (p == 0 && slot >= 0 && slot < NSLOTS) {
                    float* pb2 = g_part +
                        (((grp * N_MROWS + row) * NSLOTS) + slot) * GB + q * 8;
                    *reinterpret_cast<float4*>(pb2)     = make_float4(a0, a1, a2, a3);
                    *reinterpret_cast<float4*>(pb2 + 4) = make_float4(a4, a5, a6, a7);
                }
                pos = run_end;
            }
        }

        // ---- input-node updates (no partials needed; before cluster sync) ----
        if (gw < N_IN && lane < GB) {
            const int node = gw;
            const int b    = grp * GB + lane;
            const int nb   = node * BATCH + b;
            float phi = flux[node] + g_xT[nb] + __half2float(nzT[nb]);
            phi = fminf(fmaxf(phi, -0.5f), 0.5f);
            const float phip = (phi >= 0.5f) ? -0.5f : phi;
            const float sold = src[nb];
            const float gact = tanhf(phip) * (1.0f - sold);
            float snew = sold + DT_C * (gamma[node] * gact - sold * g_inv_tau[node]);
            snew = fminf(fmaxf(snew, -1.0f), 1.0f);
            dst[nb] = snew;
            dstm[grp * (N_TOTAL * GB) + node * GB + lane] = __float2half_rn(snew);
        }

        if (t > 0) {                  // partial visibility within cluster
            CLUSTER_ARRIVE();
            CLUSTER_WAIT();
        }

        // ---- phase 2: cluster's rows, this group's 16 batches ----
        const int bb = lane & 15;
        for (int ri = r_lo + wic * 2 + (lane >> 4); ri < r_hi; ri += 2 * CLW) {
            const int node = N_IN + ri;
            const int b    = grp * GB + bb;
            const int nb   = node * BATCH + b;
            float phi = 0.0f;
            if (t > 0) {
                const int nsl = g_row_nslots[ri];
                const float* pp =
                    g_part + ((grp * N_MROWS + ri) * NSLOTS) * GB + bb;
                #pragma unroll
                for (int sl = 0; sl < NSLOTS; ++sl)
                    if (sl < nsl) phi += pp[sl * GB];
            }
            phi += flux[node] + __half2float(nzT[nb]);
            phi = fminf(fmaxf(phi, -0.5f), 0.5f);
            const float phip = (phi >= 0.5f) ? -0.5f : phi;  // periodic wrap

            const float sold = src[nb];
            const float gact = tanhf(phip) * (1.0f - sold);
            float snew = sold + DT_C * (gamma[node] * gact - sold * g_inv_tau[node]);
            snew = fminf(fmaxf(snew, -1.0f), 1.0f);
            dst[nb] = snew;
            dstm[grp * (N_TOTAL * GB) + node * GB + bb] = __float2half_rn(snew);

            if (t == T_ITERS - 1 && node >= N_IN + N_HID)
                out[(size_t)b * N_OUT + (node - (N_IN + N_HID))] = snew;
        }
        if (t != T_ITERS - 1) grid_barrier();
    }
}

// ---------------- launch: 4 launches, main at index 3 (ncu capture slot) ----
extern "C" void kernel_launch(void* const* d_in, const int* in_sizes, int n_in,
                              void* d_out, int out_size) {
    const float* x     = (const float*)d_in[0];   // [32, 1024]
    const float* J     = (const float*)d_in[1];   // [4096, 4096]
    const float* gamma = (const float*)d_in[2];   // [4096]
    const float* tau   = (const float*)d_in[3];   // [4096]
    const float* flux  = (const float*)d_in[4];   // [4096]
    const float* mask  = (const float*)d_in[5];   // [4096, 4096]
    const float* noise = (const float*)d_in[6];   // [100, 32, 4096]
    float* out = (float*)d_out;                   // [32, 128]
    (void)in_sizes; (void)n_in; (void)out_size;

    cudaFuncSetAttribute(soen_main_kernel,
                         cudaFuncAttributeMaxDynamicSharedMemorySize, SMEM_BYTES);

    prep_kernel<<<PREP_BLKS, dim3(32, 8)>>>(mask, tau, noise, x);      // idx 0
    scan_kernel<<<1, 1024>>>();                                        // idx 1
    fill_kernel<<<(N_MROWS * 32 + 255) / 256, 256>>>(J, mask);         // idx 2

    cudaLaunchConfig_t cfg = {};                                       // idx 3
    cfg.gridDim  = dim3(MAIN_BLOCKS, 1, 1);
    cfg.blockDim = dim3(MAIN_THREADS, 1, 1);
    cfg.dynamicSmemBytes = SMEM_BYTES;
    cudaLaunchAttribute attrs[1];
    attrs[0].id = cudaLaunchAttributeClusterDimension;
    attrs[0].val.clusterDim = {2, 1, 1};
    cfg.attrs = attrs;
    cfg.numAttrs = 1;
    cudaLaunchKernelEx(&cfg, soen_main_kernel, gamma, flux, out);
}

// round 16
// speedup vs baseline: 1.4722x; 1.0285x over previous
#include <cuda_runtime.h>
#include <cuda_fp16.h>
#include <cstdint>

// ---------------- problem constants ----------------
#define N_TOTAL   4096
#define N_IN      1024
#define N_HID     2944
#define N_OUT     128
#define N_MROWS   3072          // matrix rows: nodes 1024..4095
#define BATCH     32
#define T_ITERS   100
#define DT_C      0.05f

// ---------------- kernel config --------------------
#define MAIN_BLOCKS   148
#define MAIN_THREADS  1024
#define MAIN_WARPS    (MAIN_THREADS / 32)              // 32
#define NCLUST        37                               // row-ranges per group
#define CLW           64                               // warps per 2-CTA cluster

#define NGROUPS        2                               // batch groups of 16
#define GB             16                              // batches per group

#define MAX_NNZ   (2 * 1024 * 1024)                    // expected ~815k padded
#define SMEM_CAP  368                                  // pairs per warp in smem
#define SLAB_BYTES (N_TOTAL * GB * 2)                  // 128 KB fp16 state slab
#define PAIR_BYTES (MAIN_WARPS * SMEM_CAP * 8)         // 94.2 KB
#define SMEM_BYTES (SLAB_BYTES + PAIR_BYTES)           // 220 KB < 227 KB cap
#define NSLOTS    4                                    // max chunks spanning a row

// pair word0 layout: [31:20]=row (12b), [16:5]=col*32 byte offset (col<<5)
// pair word1: J value as DUPLICATED half2 (both halves = J)
#define OFF_MASK  0x0001FFE0u

// prep mega-kernel block ranges (blockDim = 32x8 = 256)
#define PREP_NOISE_BLKS  (T_ITERS * (N_TOTAL / 64))    // 6400
#define PREP_X_BLKS      (N_IN / 32)                   // 32
#define PREP_CNT_BLKS    (N_MROWS / 8)                 // 384
#define PREP_BLKS        (PREP_NOISE_BLKS + PREP_X_BLKS + PREP_CNT_BLKS)

#define CLUSTER_ARRIVE() asm volatile("barrier.cluster.arrive.aligned;" ::: "memory")
#define CLUSTER_WAIT()   asm volatile("barrier.cluster.wait.aligned;" ::: "memory")

// ---------------- device scratch (no allocs allowed) ----------------
__device__ __align__(16) uint2 g_pairs[MAX_NNZ];   // {row<<20|col<<5, half2 J}
__device__ int  g_row_start[N_MROWS + 1];          // padded-even prefix
__device__ int  g_row_cnt[N_MROWS];                // padded (even) counts
__device__ int  g_row_w0[N_MROWS];                 // first cluster-warp covering row
__device__ int  g_row_nslots[N_MROWS];             // #chunks spanning row (0..4)
__device__ int  g_clu_row[NCLUST + 1];             // row-range boundaries
__device__ int  g_clu_base[NCLUST + 1];            // pair-index boundaries
__device__ int  g_clu_W[NCLUST];                   // per-cluster chunk size (even)

__device__ float g_part[NGROUPS * N_MROWS * NSLOTS * GB]; // [g][row][slot][16]
// fp16 mirrors, layout [g][node][16]: each group's slab is one contiguous 128KB
__device__ __align__(16) __half g_sm0[NGROUPS * N_TOTAL * GB];
__device__ __align__(16) __half g_sm1[NGROUPS * N_TOTAL * GB];
__device__ __align__(16) __half g_noiseT[(size_t)T_ITERS * N_TOTAL * BATCH]; // [t][node][b]
__device__ float g_xT[N_IN * BATCH];               // [node][b]
__device__ float g_inv_tau[N_TOTAL];

// flag barrier state (no same-address atomics -> no L2-atom serialization)
__device__ volatile unsigned g_flags[MAIN_BLOCKS];
__device__ volatile unsigned g_bar_gen;

// ---------------- software grid barrier (flag-based) ----------------
// Arrival: thread0 __threadfence (emits CCTL.IVALL -> whole-SM L1D invalidate
// + publishes this CTA's writes), then STG its flag. CTA0's warp0 polls all
// flags (volatile, L1-bypassing) and releases g_bar_gen. No loads fill L1
// between the IVALL and the release, so post-barrier plain L1-cached loads of
// cross-SM data are safe (validated rounds 6-15).
__device__ __forceinline__ void grid_barrier() {
    __syncthreads();
    if (blockIdx.x == 0) {
        if (threadIdx.x < 32) {
            if (threadIdx.x == 0) __threadfence();
            const unsigned gen = g_bar_gen;
            bool done = false;
            while (!done) {
                bool ok = true;
                for (int i = threadIdx.x; i < MAIN_BLOCKS; i += 32)
                    ok &= (i == 0) || (g_flags[i] == gen + 1u);
                done = __all_sync(0xffffffffu, ok);
            }
            if (threadIdx.x == 0) g_bar_gen = gen + 1u;
        }
        __syncthreads();
    } else {
        if (threadIdx.x == 0) {
            __threadfence();
            const unsigned gen = g_bar_gen;
            g_flags[blockIdx.x] = gen + 1u;
            while (g_bar_gen == gen) { }
        }
        __syncthreads();
    }
}

// ---------------- activation + state update (shared helper) ----------------
__device__ __forceinline__ float soen_update(float phi, float sold,
                                             float gam, float itau) {
    phi = fminf(fmaxf(phi, -0.5f), 0.5f);
    const float phip = (phi >= 0.5f) ? -0.5f : phi;   // periodic wrap
    const float gact = tanhf(phip) * (1.0f - sold);
    float snew = sold + DT_C * (gam * gact - sold * itau);
    return fminf(fmaxf(snew, -1.0f), 1.0f);
}

// ---------------- L0: mega-prep (transposes + counts + inv_tau) ----------------
__global__ void prep_kernel(const float* __restrict__ mask,
                            const float* __restrict__ tau,
                            const float* __restrict__ noise,
                            const float* __restrict__ x) {
    const unsigned blk = blockIdx.x;
    const int tx = threadIdx.x, ty = threadIdx.y;

    if (blk < PREP_NOISE_BLKS) {                   // noise transpose -> fp16
        __shared__ float tile[32][65];             // [b][node], 64 nodes
        const int t  = blk >> 6;                   // /64
        const int i0 = (blk & 63) * 64;
        for (int bb = ty; bb < 32; bb += 8) {
            const float2 v = *reinterpret_cast<const float2*>(
                noise + ((size_t)t * BATCH + bb) * N_TOTAL + i0 + 2 * tx);
            tile[bb][2 * tx]     = v.x;
            tile[bb][2 * tx + 1] = v.y;
        }
        __syncthreads();
        __half2* outp = reinterpret_cast<__half2*>(g_noiseT);
        const int l = tx & 15;
        for (int ii = ty * 2 + (tx >> 4); ii < 64; ii += 16) {
            const __half2 h = __floats2half2_rn(tile[2 * l][ii],
                                                tile[2 * l + 1][ii]);
            outp[((size_t)t * N_TOTAL + i0 + ii) * 16 + l] = h;
        }
        return;
    }
    if (blk < PREP_NOISE_BLKS + PREP_X_BLKS) {
        __shared__ float tile[32][33];
        const int xb = blk - PREP_NOISE_BLKS;
        const int i0 = xb * 32;
        for (int bb = ty; bb < 32; bb += 8)
            tile[bb][tx] = x[(size_t)bb * N_IN + i0 + tx];
        __syncthreads();
        for (int ii = ty; ii < 32; ii += 8)
            g_xT[(i0 + ii) * BATCH + tx] = tile[tx][ii];
        const int gt = xb * 256 + ty * 32 + tx;
        if (gt < N_TOTAL) g_inv_tau[gt] = 1.0f / tau[gt];
        return;
    }
    // row counts: warp per matrix row
    const int warp = (blk - PREP_NOISE_BLKS - PREP_X_BLKS) * 8 + ty;
    if (warp >= N_MROWS) return;
    const float* __restrict__ mrow = mask + (size_t)(N_IN + warp) * N_TOTAL;
    int cnt = 0;
    for (int j = tx; j < N_TOTAL; j += 32) {
        unsigned b = __ballot_sync(0xffffffffu, mrow[j] != 0.0f);
        cnt += __popc(b);
    }
    if (tx == 0) g_row_cnt[warp] = (cnt + 1) & ~1;   // pad to even
}

// ---------------- L1: prefix over padded counts + cluster row ranges ----------
__global__ void scan_kernel() {
    __shared__ int sh[32];
    const int t = threadIdx.x;      // 1024 threads
    int off = 0;
    for (int seg = 0; seg < 3; ++seg) {
        int v = g_row_cnt[seg * 1024 + t];
        int xv = v;
        #pragma unroll
        for (int d = 1; d < 32; d <<= 1) {
            int y = __shfl_up_sync(0xffffffffu, xv, d);
            if ((t & 31) >= d) xv += y;
        }
        if ((t & 31) == 31) sh[t >> 5] = xv;
        __syncthreads();
        if (t < 32) {
            int x2 = sh[t];
            #pragma unroll
            for (int d = 1; d < 32; d <<= 1) {
                int y = __shfl_up_sync(0xffffffffu, x2, d);
                if (t >= d) x2 += y;
            }
            sh[t] = x2;
        }
        __syncthreads();
        const int incl = xv + ((t >= 32) ? sh[(t >> 5) - 1] : 0);
        g_row_start[seg * 1024 + t] = off + incl - v;
        const int segtotal = sh[31];
        __syncthreads();
        off += segtotal;
    }
    const int total = off;                  // uniform across threads
    if (t == 0) g_row_start[N_MROWS] = total;
    __syncthreads();

    // cluster row boundaries: 37 weight-balanced contiguous ranges
    if (t <= NCLUST) {
        int r;
        if (t == 0) r = 0;
        else if (t == NCLUST) r = N_MROWS;
        else {
            const long long target = (long long)t * total / NCLUST;
            int lo = 0, hi = N_MROWS;       // smallest r with start[r] >= target
            while (lo < hi) {
                const int mid = (lo + hi) >> 1;
                if (g_row_start[mid] >= target) hi = mid; else lo = mid + 1;
            }
            r = lo;
        }
        g_clu_row[t]  = r;
        g_clu_base[t] = g_row_start[r];
    }
    __syncthreads();
    if (t < NCLUST) {
        const int diff = g_clu_base[t + 1] - g_clu_base[t];
        int w = (diff + CLW - 1) / CLW;
        w = (w + 1) & ~1;
        if (w < 2) w = 2;
        g_clu_W[t] = w;
    }
}

// ---------------- L2: fill flat pair array + per-row chunk metadata ----------------
__global__ void fill_kernel(const float* __restrict__ J,
                            const float* __restrict__ mask) {
    const int warp = (blockIdx.x * blockDim.x + threadIdx.x) >> 5;
    const int lane = threadIdx.x & 31;
    if (warp >= N_MROWS) return;
    const int row = N_IN + warp;
    const float* __restrict__ mrow = mask + (size_t)row * N_TOTAL;
    const float* __restrict__ jrow = J    + (size_t)row * N_TOTAL;
    const int base = g_row_start[warp];
    const unsigned rtag = (unsigned)warp << 20;

    int pos = base;
    for (int j = lane; j < N_TOTAL; j += 32) {
        const float mv = mrow[j];
        const bool  nz = (mv != 0.0f);
        unsigned b = __ballot_sync(0xffffffffu, nz);
        if (nz) {
            int idx = pos + __popc(b & ((1u << lane) - 1u));
            __half2 h2 = __float2half2_rn(jrow[j] * mv);   // duplicated fp16 J
            g_pairs[idx] = make_uint2(rtag | ((unsigned)j << 5),
                                      *reinterpret_cast<unsigned*>(&h2));
        }
        pos += __popc(b);
    }
    const int cnt = pos - base;
    if (lane == 0) {
        if (cnt & 1) g_pairs[base + cnt] = make_uint2(rtag, 0u);  // pad, val=0
        const int cnt_pad = (cnt + 1) & ~1;
        int k = 0;
        while (k < NCLUST - 1 && base >= g_clu_base[k + 1]) ++k;
        const int Wk = g_clu_W[k];
        int w0 = 0, nsl = 0;
        if (cnt_pad > 0) {
            w0  = (base - g_clu_base[k]) / Wk;
            nsl = (base + cnt_pad - 1 - g_clu_base[k]) / Wk - w0 + 1;
            if (nsl > NSLOTS) nsl = NSLOTS;
        }
        g_row_w0[warp]     = w0;
        g_row_nslots[warp] = nsl;
    }
}

// ---------------- L3: main persistent recurrence kernel ----------------
// Grid 148, cluster (2,1,1): cluster c owns batch-group g=c&1 and row range
// k=c>>1. CTA keeps its group's fp16 state slab [4096][16] (128 KB smem),
// refilled per iter from the fp16 mirror. fp32 state lives ONLY in registers:
// the phase2 row->thread map is static, so each thread carries its rows' fp32
// states across iterations (no fp32 state arrays at all).
// Phase1: HFMA2 accumulation over smem-staged pair chunks (R15-validated).
// Static per-row constants (flux/gamma/inv_tau/nslots/partial ptr) cached in
// registers before the t-loop; noise + secondary-row constants prefetched
// BEFORE the cluster barrier to hide L2 latency behind the wait.
__global__ void __launch_bounds__(MAIN_THREADS, 1)
soen_main_kernel(const float* __restrict__ gamma,
                 const float* __restrict__ flux,
                 float* __restrict__ out) {
    extern __shared__ char smem_raw[];
    char*  slab     = smem_raw;                        // 128 KB fp16 state
    uint2* sh_pairs = (uint2*)(smem_raw + SLAB_BYTES); // pair chunks

    const int lane = threadIdx.x & 31;
    const int wcta = threadIdx.x >> 5;
    const int cid  = blockIdx.x >> 1;                  // cluster 0..73
    const int grp  = cid & 1;                          // batch group
    const int kcl  = cid >> 1;                         // row-range 0..36
    const int wic  = (blockIdx.x & 1) * 32 + wcta;     // warp-in-cluster 0..63
    const int p    = lane >> 1;                        // nnz position 0..15
    const int q    = lane & 1;                         // batch octet 0..1

    const int Wk    = g_clu_W[kcl];
    const int cb    = g_clu_base[kcl];
    const int cend  = g_clu_base[kcl + 1];
    const int cbase = cb + wic * Wk;
    int n = cend - cbase;
    if (n > Wk) n = Wk;
    if (n < 0) n = 0;

    // stage this warp's pair chunk into smem (once; static schedule)
    const uint2* __restrict__ pbase;
    if (Wk <= SMEM_CAP) {
        uint2* mych = sh_pairs + wcta * SMEM_CAP;
        for (int j = lane; j < n; j += 32) mych[j] = g_pairs[cbase + j];
        __syncwarp();
        pbase = mych;
    } else {
        pbase = g_pairs + cbase;       // fallback (not expected)
    }

    const int r_lo = g_clu_row[kcl];
    const int r_hi = g_clu_row[kcl + 1];
    const int gw   = kcl * CLW + wic;                  // group-warp id (input map)
    const int bb   = lane & 15;
    const int b    = grp * GB + bb;

    // ---- static row ownership + cached constants (phase2 map is static) ----
    const int  ri0   = r_lo + wic * 2 + (lane >> 4);
    const int  ri1   = ri0 + 2 * CLW;
    const int  ri2   = ri1 + 2 * CLW;                  // safety (never expected)
    const bool own0  = ri0 < r_hi;
    const bool own1  = ri1 < r_hi;
    const bool own2  = ri2 < r_hi;
    const int  node0 = N_IN + ri0;

    float flux0 = 0.f, gam0 = 0.f, itau0 = 0.f;
    int   nsl0  = 0;
    const float* pp0 = g_part;
    if (own0) {
        flux0 = flux[node0];
        gam0  = gamma[node0];
        itau0 = g_inv_tau[node0];
        nsl0  = g_row_nslots[ri0];
        pp0   = g_part + ((grp * N_MROWS + ri0) * NSLOTS) * GB + bb;
    }
    const bool ownIn = (gw < N_IN) && (lane < GB);
    float biasI = 0.f, gamI = 0.f, itauI = 0.f;
    if (ownIn) {
        biasI = flux[gw] + g_xT[gw * BATCH + b];
        gamI  = gamma[gw];
        itauI = g_inv_tau[gw];
    }

    float s_own0 = 0.f, s_own1 = 0.f, s_own2 = 0.f, s_in = 0.f; // register state

    for (int t = 0; t < T_ITERS; ++t) {
        const __half* srcm = (t & 1) ? g_sm1 : g_sm0;
        __half*       dstm = (t & 1) ? g_sm0 : g_sm1;
        const __half* __restrict__ nzT = g_noiseT + (size_t)t * (N_TOTAL * BATCH);

        if (t > 0) {
            // ---- slab fill: 128 KB straight copy (mirror layout == slab) ----
            {
                const uint4* __restrict__ ms =
                    reinterpret_cast<const uint4*>(srcm + grp * (N_TOTAL * GB));
                uint4* md = reinterpret_cast<uint4*>(slab);
                #pragma unroll
                for (int r = 0; r < SLAB_BYTES / 16 / MAIN_THREADS; ++r) {
                    const int i = r * MAIN_THREADS + threadIdx.x;
                    md[i] = __ldcg(ms + i);
                }
            }
            __syncthreads();

            // ---- phase 1: balanced SpMM partials (HFMA2 on SMEM gathers) ----
            int pos = 0;
            while (pos < n) {
                const unsigned h0 = pbase[pos].x;
                const int row = (int)(h0 >> 20);
                int run_end = g_row_start[row + 1] - cbase;
                if (run_end > n) run_end = n;
                const int slot = wic - g_row_w0[row];

                __half2 c0 = __float2half2_rn(0.0f);
                __half2 c1 = c0, c2 = c0, c3 = c0;
                for (int kk = pos; kk < run_end; kk += 16) {
                    const int idx = kk + p;
                    if (idx < run_end) {
                        const uint2 pr = pbase[idx];
                        const uint4 hv = *reinterpret_cast<const uint4*>(
                            slab + (pr.x & OFF_MASK) + q * 16);
                        const __half2 jv = *reinterpret_cast<const __half2*>(&pr.y);
                        c0 = __hfma2(jv, *reinterpret_cast<const __half2*>(&hv.x), c0);
                        c1 = __hfma2(jv, *reinterpret_cast<const __half2*>(&hv.y), c1);
                        c2 = __hfma2(jv, *reinterpret_cast<const __half2*>(&hv.z), c2);
                        c3 = __hfma2(jv, *reinterpret_cast<const __half2*>(&hv.w), c3);
                    }
                }
                const float2 f0 = __half22float2(c0);
                const float2 f1 = __half22float2(c1);
                const float2 f2 = __half22float2(c2);
                const float2 f3 = __half22float2(c3);
                float a0 = f0.x, a1 = f0.y, a2 = f1.x, a3 = f1.y;
                float a4 = f2.x, a5 = f2.y, a6 = f3.x, a7 = f3.y;
                // reduce across nnz positions (lane bits 1..4) in fp32
                #pragma unroll
                for (int d = 2; d < 32; d <<= 1) {
                    a0 += __shfl_xor_sync(0xffffffffu, a0, d);
                    a1 += __shfl_xor_sync(0xffffffffu, a1, d);
                    a2 += __shfl_xor_sync(0xffffffffu, a2, d);
                    a3 += __shfl_xor_sync(0xffffffffu, a3, d);
                    a4 += __shfl_xor_sync(0xffffffffu, a4, d);
                    a5 += __shfl_xor_sync(0xffffffffu, a5, d);
                    a6 += __shfl_xor_sync(0xffffffffu, a6, d);
                    a7 += __shfl_xor_sync(0xffffffffu, a7, d);
                }
                if (p == 0 && slot >= 0 && slot < NSLOTS) {
                    float* pb2 = g_part +
                        (((grp * N_MROWS + row) * NSLOTS) + slot) * GB + q * 8;
                    *reinterpret_cast<float4*>(pb2)     = make_float4(a0, a1, a2, a3);
                    *reinterpret_cast<float4*>(pb2 + 4) = make_float4(a4, a5, a6, a7);
                }
                pos = run_end;
            }
        }

        // ---- input-node updates (register state; before cluster sync) ----
        if (ownIn) {
            const float phi = biasI + __half2float(nzT[gw * BATCH + b]);
            s_in = soen_update(phi, s_in, gamI, itauI);
            dstm[grp * (N_TOTAL * GB) + gw * GB + lane] = __float2half_rn(s_in);
        }

        // ---- prefetch phase2 inputs BEFORE the barrier (hide L2 latency) ----
        float nz0 = 0.f, nz1 = 0.f, nz2 = 0.f;
        float flux1 = 0.f, gam1 = 0.f, itau1 = 0.f;
        float flux2 = 0.f, gam2 = 0.f, itau2 = 0.f;
        int   nsl1 = 0, nsl2 = 0;
        if (own0) nz0 = __half2float(nzT[node0 * BATCH + b]);
        if (own1) {
            const int node1 = N_IN + ri1;
            nz1   = __half2float(nzT[node1 * BATCH + b]);
            flux1 = flux[node1];
            gam1  = gamma[node1];
            itau1 = g_inv_tau[node1];
            nsl1  = g_row_nslots[ri1];
        }
        if (own2) {
            const int node2 = N_IN + ri2;
            nz2   = __half2float(nzT[node2 * BATCH + b]);
            flux2 = flux[node2];
            gam2  = gamma[node2];
            itau2 = g_inv_tau[node2];
            nsl2  = g_row_nslots[ri2];
        }

        if (t > 0) {                  // partial visibility within cluster
            CLUSTER_ARRIVE();
            CLUSTER_WAIT();
        }

        // ---- phase 2: owned rows, register-resident state ----
        if (own0) {
            float phi = flux0 + nz0;
            if (t > 0) {
                #pragma unroll
                for (int sl = 0; sl < NSLOTS; ++sl)
                    if (sl < nsl0) phi += pp0[sl * GB];
            }
            s_own0 = soen_update(phi, s_own0, gam0, itau0);
            dstm[grp * (N_TOTAL * GB) + node0 * GB + bb] = __float2half_rn(s_own0);
            if (t == T_ITERS - 1 && node0 >= N_IN + N_HID)
                out[(size_t)b * N_OUT + (node0 - (N_IN + N_HID))] = s_own0;
        }
        if (own1) {
            const int node1 = N_IN + ri1;
            float phi = flux1 + nz1;
            if (t > 0) {
                const float* pp1 =
                    g_part + ((grp * N_MROWS + ri1) * NSLOTS) * GB + bb;
                #pragma unroll
                for (int sl = 0; sl < NSLOTS; ++sl)
                    if (sl < nsl1) phi += pp1[sl * GB];
            }
            s_own1 = soen_update(phi, s_own1, gam1, itau1);
            dstm[grp * (N_TOTAL * GB) + node1 * GB + bb] = __float2half_rn(s_own1);
            if (t == T_ITERS - 1 && node1 >= N_IN + N_HID)
                out[(size_t)b * N_OUT + (node1 - (N_IN + N_HID))] = s_own1;
        }
        if (own2) {
            const int node2 = N_IN + ri2;
            float phi = flux2 + nz2;
            if (t > 0) {
                const float* pp2 =
                    g_part + ((grp * N_MROWS + ri2) * NSLOTS) * GB + bb;
                #pragma unroll
                for (int sl = 0; sl < NSLOTS; ++sl)
                    if (sl < nsl2) phi += pp2[sl * GB];
            }
            s_own2 = soen_update(phi, s_own2, gam2, itau2);
            dstm[grp * (N_TOTAL * GB) + node2 * GB + bb] = __float2half_rn(s_own2);
            if (t == T_ITERS - 1 && node2 >= N_IN + N_HID)
                out[(size_t)b * N_OUT + (node2 - (N_IN + N_HID))] = s_own2;
        }
        if (t != T_ITERS - 1) grid_barrier();
    }
}

// ---------------- launch: 4 launches, main at index 3 (ncu capture slot) ----
extern "C" void kernel_launch(void* const* d_in, const int* in_sizes, int n_in,
                              void* d_out, int out_size) {
    const float* x     = (const float*)d_in[0];   // [32, 1024]
    const float* J     = (const float*)d_in[1];   // [4096, 4096]
    const float* gamma = (const float*)d_in[2];   // [4096]
    const float* tau   = (const float*)d_in[3];   // [4096]
    const float* flux  = (const float*)d_in[4];   // [4096]
    const float* mask  = (const float*)d_in[5];   // [4096, 4096]
    const float* noise = (const float*)d_in[6];   // [100, 32, 4096]
    float* out = (float*)d_out;                   // [32, 128]
    (void)in_sizes; (void)n_in; (void)out_size;

    cudaFuncSetAttribute(soen_main_kernel,
                         cudaFuncAttributeMaxDynamicSharedMemorySize, SMEM_BYTES);

    prep_kernel<<<PREP_BLKS, dim3(32, 8)>>>(mask, tau, noise, x);      // idx 0
    scan_kernel<<<1, 1024>>>();                                        // idx 1
    fill_kernel<<<(N_MROWS * 32 + 255) / 256, 256>>>(J, mask);         // idx 2

    cudaLaunchConfig_t cfg = {};                                       // idx 3
    cfg.gridDim  = dim3(MAIN_BLOCKS, 1, 1);
    cfg.blockDim = dim3(MAIN_THREADS, 1, 1);
    cfg.dynamicSmemBytes = SMEM_BYTES;
    cudaLaunchAttribute attrs[1];
    attrs[0].id = cudaLaunchAttributeClusterDimension;
    attrs[0].val.clusterDim = {2, 1, 1};
    cfg.attrs = attrs;
    cfg.numAttrs = 1;
    cudaLaunchKernelEx(&cfg, soen_main_kernel, gamma, flux, out);
}